// round 12
// baseline (speedup 1.0000x reference)
#include <cuda_runtime.h>
#include <cuda_fp16.h>
#include <cstdint>
#include <math.h>

// ---------------- problem constants ----------------
#define HW      16384
#define CH      256
#define NANCH   147456
#define TOPK    6000
#define POSTK   300
#define STRIDE  8.0f
#define IMSZ    1024.0f
#define DWCLIP  4.135166556742356f
#define MINSZ   16.0f
// exact comparison constant: midpoint(0.7f, nextafterf(0.7f)); RN(q)>0.7f <=> q>=MTHR
#define MTHR    0x1.666667p-1

#define PADW    132
#define PADH    130
#define PADHW   (PADW*PADH)

#define NSEL    8192
#define NBITW   188

// conv tiling (unchanged, passing)
#define NSTAGE  36
#define RSB     144
#define RSW     36
#define A_SEC   18432
#define B_SEC   36864
#define BUFB    (2*A_SEC + 2*B_SEC)
#define DYNSM   (2*BUFB)

// tail
#define GRIDT   148
#define TAILSM  121088      // max(16KB hist/sort, 5*6000*4 + 188*4 NMS)

// ---------------- scratch ----------------
__device__ float g_rpnfeat[CH * HW];
__device__ __align__(256) __half g_tb[2 * PADHW * 256];
__device__ __align__(256) __half g_wa[2 * 9 * 256 * 256];
__device__ float g_boxes[NANCH * 4];            // raw deltas + bias
__device__ unsigned long long g_keys[NANCH];
__device__ unsigned long long g_sel[NSEL];
__device__ float g_dx1[NANCH], g_dy1[NANCH], g_dx2[NANCH], g_dy2[NANCH], g_dar[NANCH];
__device__ int g_hist1[4096];
__device__ int g_hist2[4096];
__device__ int g_B1;
__device__ int g_cntgt;
__device__ unsigned g_T;
__device__ int g_selcnt;
__device__ int g_bars[64];

// ---------------- helpers ----------------
__device__ __forceinline__ uint32_t smem_u32(const void* p) {
    uint32_t a;
    asm("{ .reg .u64 t; cvta.to.shared.u64 t, %1; cvt.u32.u64 %0, t; }" : "=r"(a) : "l"(p));
    return a;
}
#define CP_ASYNC16(dst, src) \
    asm volatile("cp.async.cg.shared.global [%0], [%1], 16;" :: "r"(dst), "l"(src))
#define CP_COMMIT()  asm volatile("cp.async.commit_group;" ::: "memory")
#define CP_WAIT0()   asm volatile("cp.async.wait_group 0;" ::: "memory")

#define MMA16816(d, a, b) \
    asm volatile("mma.sync.aligned.m16n8k16.row.col.f32.f16.f16.f32 " \
        "{%0,%1,%2,%3}, {%4,%5,%6,%7}, {%8,%9}, {%0,%1,%2,%3};" \
        : "+f"((d)[0]), "+f"((d)[1]), "+f"((d)[2]), "+f"((d)[3]) \
        : "r"((a)[0]), "r"((a)[1]), "r"((a)[2]), "r"((a)[3]), "r"((b)[0]), "r"((b)[1]))

__device__ __forceinline__ void gsync(int k) {
    __threadfence();
    __syncthreads();
    if (threadIdx.x == 0) {
        atomicAdd(&g_bars[k], 1);
        while (atomicAdd(&g_bars[k], 0) < GRIDT) { __nanosleep(64); }
    }
    __syncthreads();
}
// barrier among blocks 0..3 only
__device__ __forceinline__ void sync4(int k) {
    __threadfence();
    __syncthreads();
    if (threadIdx.x == 0) {
        atomicAdd(&g_bars[k], 1);
        while (atomicAdd(&g_bars[k], 0) < 4) { __nanosleep(32); }
    }
    __syncthreads();
}

// =====================================================================
// fused prep (unchanged from R11, passing)
// =====================================================================
__global__ __launch_bounds__(1024)
void prep_all(const float* __restrict__ feat, const float* __restrict__ w)
{
    __shared__ float sm[32][33];
    const int b = blockIdx.x;
    const int tid = threadIdx.x;

    if (b < 4096) {
        const int px0 = (b & 511) << 5;
        const int ic0 = (b >> 9) << 5;
        const int tx = tid & 31, ty = tid >> 5;
        sm[ty][tx] = feat[(ic0 + ty) * HW + px0 + tx];
        __syncthreads();
        float v = sm[tx][ty];
        __half h0 = __float2half_rn(v);
        __half h1 = __float2half_rn(v - __half2float(h0));
        const int p = px0 + ty;
        const int padpos = ((p >> 7) + 1) * PADW + (p & 127) + 1;
        const int waddr = padpos * 256 + ic0 + tx;
        g_tb[waddr] = h0;
        g_tb[PADHW * 256 + waddr] = h1;
    } else if (b < 4160) {
        int idx = (b - 4096) * 1024 + tid;
        int oc = idx >> 8, ic = idx & 255;
#pragma unroll
        for (int tap = 0; tap < 9; tap++) {
            float x = w[oc * 2304 + ic * 9 + tap];
            __half h0 = __float2half_rn(x);
            __half h1 = __float2half_rn(x - __half2float(h0));
            int base = (tap * 256 + oc) * 256 + ic;
            g_wa[base] = h0;
            g_wa[9 * 65536 + base] = h1;
        }
    } else if (b < 4354) {
        int gid = (b - 4160) * 1024 + tid;
        if (gid < 776 * 256) {
            int hid = gid >> 8, ic = gid & 255;
            int yp, xp;
            if (hid < 132)      { yp = 0;   xp = hid; }
            else if (hid < 264) { yp = 129; xp = hid - 132; }
            else {
                int r = hid - 264;
                yp = 1 + (r >> 2);
                int c = r & 3;
                xp = (c == 0) ? 0 : 128 + c;
            }
            int base = (yp * PADW + xp) * 256 + ic;
            g_tb[base] = __float2half_rn(0.f);
            g_tb[PADHW * 256 + base] = __float2half_rn(0.f);
        }
    } else {
        int gid = (b - 4354) * 1024 + tid;
        if (gid < 4096) g_hist1[gid] = 0;
        else if (gid < 8192) g_hist2[gid - 4096] = 0;
        else if (gid < 16384) g_sel[gid - 8192] = 0ull;
        else if (gid < 16448) g_bars[gid - 16384] = 0;
        else if (gid == 16448) g_selcnt = 0;
        else if (gid == 16449) g_B1 = 0;
        else if (gid == 16450) g_cntgt = 0;
        else if (gid == 16451) g_T = 0u;
    }
}

// =====================================================================
// conv (unchanged, passing)
// =====================================================================
__device__ __forceinline__ void issue_stage(uint32_t sbase, int s, int tid, int yblk, int oc0)
{
    const int tap = s >> 2;
    const int icb = (s & 3) << 7;
    const int ky = tap / 3, kx = tap - ky * 3;
#pragma unroll
    for (int i = 0; i < 12; i++) {
        int cid = tid + (i << 9);
        int row = cid >> 3, c = cid & 7;
        const char* src;
        uint32_t dst;
        if (row < 256) {
            int sp = row >> 7, r = row & 127;
            src = (const char*)g_wa + ((sp * 9 + tap) * 256 + oc0 + r) * 512 + icb;
            dst = sbase + sp * A_SEC + r * RSB;
        } else {
            int rowb = row - 256;
            int sp = rowb >> 8, p = rowb & 255;
            int yy = (yblk << 1) + (p >> 7) + ky;
            int xx = (p & 127) + kx;
            src = (const char*)g_tb + (sp * PADHW + yy * PADW + xx) * 512 + icb;
            dst = sbase + 2 * A_SEC + sp * B_SEC + p * RSB;
        }
        CP_ASYNC16(dst + c * 16, src + c * 16);
    }
    CP_COMMIT();
}

__global__ void __launch_bounds__(512, 1) conv_mma(const float* __restrict__ bias)
{
    extern __shared__ char dsm[];
    const uint32_t smem_base = smem_u32(dsm);
    const int tid = threadIdx.x;
    const int yblk = blockIdx.x;
    const int oc0 = blockIdx.y << 7;
    const int wid = tid >> 5, lane = tid & 31;
    const int wm = wid & 3, wn = wid >> 2;
    const int g = lane >> 2, t = lane & 3;

    float acc[2][8][4];
#pragma unroll
    for (int mt = 0; mt < 2; mt++)
#pragma unroll
        for (int nt = 0; nt < 8; nt++)
#pragma unroll
            for (int c = 0; c < 4; c++) acc[mt][nt][c] = 0.f;

    issue_stage(smem_base, 0, tid, yblk, oc0);
    CP_WAIT0();
    __syncthreads();

    for (int s = 0; s < NSTAGE; s++) {
        if (s + 1 < NSTAGE)
            issue_stage(smem_base + ((s + 1) & 1) * BUFB, s + 1, tid, yblk, oc0);

        const uint32_t* smw = (const uint32_t*)(dsm + (s & 1) * BUFB);
#pragma unroll
        for (int k16 = 0; k16 < 4; k16++) {
            const int ko = k16 * 8 + t;
            uint32_t af[2][2][4];
#pragma unroll
            for (int sp = 0; sp < 2; sp++)
#pragma unroll
                for (int mt = 0; mt < 2; mt++) {
                    int row = wm * 32 + mt * 16 + g;
                    int base = sp * (A_SEC / 4) + row * RSW + ko;
                    af[sp][mt][0] = smw[base];
                    af[sp][mt][1] = smw[base + 8 * RSW];
                    af[sp][mt][2] = smw[base + 4];
                    af[sp][mt][3] = smw[base + 8 * RSW + 4];
                }
#pragma unroll
            for (int sb = 0; sb < 2; sb++) {
                uint32_t bf_[8][2];
#pragma unroll
                for (int nt = 0; nt < 8; nt++) {
                    int n = wn * 64 + nt * 8 + g;
                    int base = 2 * (A_SEC / 4) + sb * (B_SEC / 4) + n * RSW + ko;
                    bf_[nt][0] = smw[base];
                    bf_[nt][1] = smw[base + 4];
                }
                const int nsa = (sb == 0) ? 2 : 1;
#pragma unroll
                for (int sa = 0; sa < 2; sa++) {
                    if (sa < nsa) {
#pragma unroll
                        for (int mt = 0; mt < 2; mt++)
#pragma unroll
                            for (int nt = 0; nt < 8; nt++)
                                MMA16816(acc[mt][nt], af[sa][mt], bf_[nt]);
                    }
                }
            }
        }

        if (s + 1 < NSTAGE) {
            CP_WAIT0();
            __syncthreads();
        }
    }

#pragma unroll
    for (int mt = 0; mt < 2; mt++) {
        int ocl = oc0 + wm * 32 + mt * 16 + g;
        float b0 = bias[ocl];
        float b1 = bias[ocl + 8];
#pragma unroll
        for (int nt = 0; nt < 8; nt++) {
            int col = wn * 64 + nt * 8 + 2 * t;
            float2 lo, hi;
            lo.x = fmaxf(acc[mt][nt][0] + b0, 0.f);
            lo.y = fmaxf(acc[mt][nt][1] + b0, 0.f);
            hi.x = fmaxf(acc[mt][nt][2] + b1, 0.f);
            hi.y = fmaxf(acc[mt][nt][3] + b1, 0.f);
            *(float2*)&g_rpnfeat[ocl * HW + yblk * 256 + col] = lo;
            *(float2*)&g_rpnfeat[(ocl + 8) * HW + yblk * 256 + col] = hi;
        }
    }
}

// =====================================================================
// heads (unchanged, passing)
// =====================================================================
#define HSM_FLOATS (11520 + 720)
#define HSM_BYTES  (HSM_FLOATS * 4)

__global__ __launch_bounds__(256)
void heads_sums(const float* __restrict__ cls_w, const float* __restrict__ cls_b,
                const float* __restrict__ bbox_w, const float* __restrict__ bbox_b)
{
    extern __shared__ float hsm[];
    float* ws   = hsm;
    float* red  = hsm;
    float* sums = hsm + 11520;

    const int tid = threadIdx.x;
    for (int i = tid; i < 9 * 256; i += 256)  ws[(i >> 8) * 256 + (i & 255)] = cls_w[i];
    for (int i = tid; i < 36 * 256; i += 256) ws[(9 + (i >> 8)) * 256 + (i & 255)] = bbox_w[i];
    __syncthreads();

    const int pl = tid & 15;
    const int q  = tid >> 4;
    const int p  = (blockIdx.x << 4) + pl;

    float acc[45];
#pragma unroll
    for (int j = 0; j < 45; j++) acc[j] = 0.f;

    const float* rf = g_rpnfeat + (q << 4) * HW + p;
    const float* wq = ws + (q << 4);
#pragma unroll
    for (int cc = 0; cc < 16; cc++) {
        float v = rf[cc * HW];
#pragma unroll
        for (int j = 0; j < 45; j++) acc[j] = fmaf(wq[j * 256 + cc], v, acc[j]);
    }
    __syncthreads();

    {
        float* r = red + (q * 16 + pl) * 45;
#pragma unroll
        for (int j = 0; j < 45; j++) r[j] = acc[j];
    }
    __syncthreads();

    for (int task = tid; task < 720; task += 256) {
        int pl2 = task / 45, j = task - pl2 * 45;
        float s = 0.f;
#pragma unroll
        for (int q2 = 0; q2 < 16; q2++)
            s += red[(q2 * 16 + pl2) * 45 + j];
        sums[pl2 * 45 + j] = s;
    }
    __syncthreads();

    if (tid < 144) {
        int pxl = tid / 9;
        int a   = tid - pxl * 9;
        const float* s = sums + pxl * 45;
        int pg = (blockIdx.x << 4) + pxl;
        int idx = pg * 9 + a;

        g_boxes[idx * 4 + 0] = s[9 + a * 4 + 0] + bbox_b[a * 4 + 0];
        g_boxes[idx * 4 + 1] = s[9 + a * 4 + 1] + bbox_b[a * 4 + 1];
        g_boxes[idx * 4 + 2] = s[9 + a * 4 + 2] + bbox_b[a * 4 + 2];
        g_boxes[idx * 4 + 3] = s[9 + a * 4 + 3] + bbox_b[a * 4 + 3];

        float cls = s[a] + cls_b[a];
        unsigned bb = __float_as_uint(cls);
        unsigned u = (bb & 0x80000000u) ? ~bb : (bb | 0x80000000u);
        g_keys[idx] = ((unsigned long long)u << 32) | (unsigned)(0xFFFFFFFFu - (unsigned)idx);
    }
}

// =====================================================================
// TAIL: select -> decode(parallel) -> sort(4 blocks) -> NMS(block 0)
// =====================================================================
__device__ void scan_phase(int* s, const int* h, int base, int phase)
{
    const int t = threadIdx.x;
    int c0 = h[4 * t], c1 = h[4 * t + 1], c2 = h[4 * t + 2], c3 = h[4 * t + 3];
    int v = c0 + c1 + c2 + c3;
    s[t] = v;
    __syncthreads();
    for (int off = 1; off < 1024; off <<= 1) {
        int add = (t + off < 1024) ? s[t + off] : 0;
        __syncthreads();
        v += add;
        s[t] = v;
        __syncthreads();
    }
    int suff = s[t];
    int above = (t < 1023) ? s[t + 1] : 0;
    if (base + above < TOPK && base + suff >= TOPK) {
        int cum = base + above;
        int c[4] = {c0, c1, c2, c3};
#pragma unroll
        for (int b = 3; b >= 0; b--) {
            if (cum + c[b] >= TOPK) {
                if (phase == 0) { g_B1 = 4 * t + b; g_cntgt = cum; }
                else            { g_T = ((unsigned)g_B1 << 12) | (unsigned)(4 * t + b); }
                break;
            }
            cum += c[b];
        }
    }
    __syncthreads();
}

__global__ __launch_bounds__(1024)
void tail(float* __restrict__ out)
{
    extern __shared__ char dsm[];
    const int tid = threadIdx.x;
    const int b = blockIdx.x;

    // ---- A: hist1 ----
    {
        int* h = (int*)dsm;
        for (int i = tid; i < 4096; i += 1024) h[i] = 0;
        __syncthreads();
        for (int i = b * 1024 + tid; i < NANCH; i += GRIDT * 1024)
            atomicAdd(&h[(unsigned)(g_keys[i] >> 52)], 1);
        __syncthreads();
        for (int i = tid; i < 4096; i += 1024) {
            int v = h[i];
            if (v) atomicAdd(&g_hist1[i], v);
        }
    }
    gsync(0);
    if (b == 0) scan_phase((int*)dsm, g_hist1, 0, 0);
    gsync(1);
    {
        const unsigned b1 = (unsigned)(*(volatile int*)&g_B1);
        int* h = (int*)dsm;
        for (int i = tid; i < 4096; i += 1024) h[i] = 0;
        __syncthreads();
        for (int i = b * 1024 + tid; i < NANCH; i += GRIDT * 1024) {
            unsigned long long key = g_keys[i];
            if ((unsigned)(key >> 52) == b1)
                atomicAdd(&h[(unsigned)((key >> 40) & 0xFFFull)], 1);
        }
        __syncthreads();
        for (int i = tid; i < 4096; i += 1024) {
            int v = h[i];
            if (v) atomicAdd(&g_hist2[i], v);
        }
    }
    gsync(2);
    if (b == 0) scan_phase((int*)dsm, g_hist2, *(volatile int*)&g_cntgt, 1);
    gsync(3);

    // ---- E: compact + parallel decode ----
    {
        const float AR[3]  = {0.5f, 1.0f, 2.0f};
        const float SCL[3] = {128.f, 256.f, 512.f};
        const unsigned T = *(volatile unsigned*)&g_T;
        for (int i = b * 1024 + tid; i < NANCH; i += GRIDT * 1024) {
            unsigned long long key = g_keys[i];
            if ((unsigned)(key >> 40) >= T) {
                int p = atomicAdd(&g_selcnt, 1);
                if (p < NSEL) g_sel[p] = key;

                // decode anchor i into per-anchor arrays
                float4 d = *(const float4*)&g_boxes[i * 4];
                int pg = i / 9;
                int a = i - pg * 9;
                float sx = (float)(pg & 127) * STRIDE;
                float sy = (float)(pg >> 7) * STRIDE;
                int ia = a / 3, is_ = a - ia * 3;
                float hr  = sqrtf(AR[ia]);
                float wr  = __frcp_rn(hr);
                float hsv = __fmul_rn(hr, SCL[is_]);
                float wsv = __fmul_rn(wr, SCL[is_]);
                float bx1 = rintf(__fmul_rn(-wsv, 0.5f));
                float by1 = rintf(__fmul_rn(-hsv, 0.5f));
                float bx2 = rintf(__fmul_rn(wsv, 0.5f));
                float by2 = rintf(__fmul_rn(hsv, 0.5f));
                float ax1 = __fadd_rn(sx, bx1), ay1 = __fadd_rn(sy, by1);
                float ax2 = __fadd_rn(sx, bx2), ay2 = __fadd_rn(sy, by2);
                float aw = __fsub_rn(ax2, ax1), ah = __fsub_rn(ay2, ay1);
                float cx = __fadd_rn(ax1, __fmul_rn(0.5f, aw));
                float cy = __fadd_rn(ay1, __fmul_rn(0.5f, ah));

                float dw = fminf(d.z, DWCLIP);
                float dh = fminf(d.w, DWCLIP);
                float px = __fadd_rn(__fmul_rn(d.x, aw), cx);
                float py = __fadd_rn(__fmul_rn(d.y, ah), cy);
                float pw = __fmul_rn((float)exp((double)dw), aw);
                float ph = __fmul_rn((float)exp((double)dh), ah);

                float x1 = __fsub_rn(px, __fmul_rn(0.5f, pw));
                float y1 = __fsub_rn(py, __fmul_rn(0.5f, ph));
                float x2 = __fadd_rn(px, __fmul_rn(0.5f, pw));
                float y2 = __fadd_rn(py, __fmul_rn(0.5f, ph));

                x1 = fminf(fmaxf(x1, 0.f), IMSZ);
                y1 = fminf(fmaxf(y1, 0.f), IMSZ);
                x2 = fminf(fmaxf(x2, 0.f), IMSZ);
                y2 = fminf(fmaxf(y2, 0.f), IMSZ);
                float wv = __fsub_rn(x2, x1);
                float hv = __fsub_rn(y2, y1);
                float ar = __fmul_rn(wv, hv);
                if (!(wv >= MINSZ && hv >= MINSZ)) ar = -1.f;   // invalid sentinel

                g_dx1[i] = x1; g_dy1[i] = y1; g_dx2[i] = x2; g_dy2[i] = y2; g_dar[i] = ar;
            }
        }
    }

    // ---- barrier 4: all arrive; blocks >=4 exit ----
    __threadfence();
    __syncthreads();
    if (tid == 0) atomicAdd(&g_bars[4], 1);
    if (b >= 4) return;
    if (tid == 0) { while (atomicAdd(&g_bars[4], 0) < GRIDT) { __nanosleep(64); } }
    __syncthreads();

    // ---- F1: parallel sort on blocks 0-3 ----
    unsigned long long* sk = (unsigned long long*)dsm;
    const int cbase = b << 11;   // 2048-key chunk

    // local bitonic k=2..2048
    sk[tid]        = g_sel[cbase + tid];
    sk[tid + 1024] = g_sel[cbase + tid + 1024];
    __syncthreads();
    for (int k = 2; k <= 2048; k <<= 1) {
        for (int j = k >> 1; j > 0; j >>= 1) {
            int t = tid;
            int i = (t << 1) - (t & (j - 1));
            bool desc = (((cbase + i) & k) == 0);
            unsigned long long x = sk[i], y = sk[i + j];
            if ((x < y) == desc) { sk[i] = y; sk[i + j] = x; }
            __syncthreads();
        }
    }
    g_sel[cbase + tid]        = sk[tid];
    g_sel[cbase + tid + 1024] = sk[tid + 1024];
    sync4(10);

    // cross k=4096, j=2048
    {
        int t4 = (b << 10) + tid;                  // 0..4095
        int i = (t4 << 1) - (t4 & 2047);
        bool desc = ((i & 4096) == 0);
        unsigned long long x = g_sel[i], y = g_sel[i + 2048];
        if ((x < y) == desc) { g_sel[i] = y; g_sel[i + 2048] = x; }
    }
    sync4(11);

    // local finish k=4096, j=1024..1
    sk[tid]        = g_sel[cbase + tid];
    sk[tid + 1024] = g_sel[cbase + tid + 1024];
    __syncthreads();
    for (int j = 1024; j > 0; j >>= 1) {
        int t = tid;
        int i = (t << 1) - (t & (j - 1));
        bool desc = (((cbase + i) & 4096) == 0);
        unsigned long long x = sk[i], y = sk[i + j];
        if ((x < y) == desc) { sk[i] = y; sk[i + j] = x; }
        __syncthreads();
    }
    g_sel[cbase + tid]        = sk[tid];
    g_sel[cbase + tid + 1024] = sk[tid + 1024];
    sync4(12);

    // cross k=8192, j=4096 (all desc)
    {
        int t4 = (b << 10) + tid;
        unsigned long long x = g_sel[t4], y = g_sel[t4 + 4096];
        if (x < y) { g_sel[t4] = y; g_sel[t4 + 4096] = x; }
    }
    sync4(13);

    // cross k=8192, j=2048
    {
        int t4 = (b << 10) + tid;
        int i = (t4 << 1) - (t4 & 2047);
        unsigned long long x = g_sel[i], y = g_sel[i + 2048];
        if (x < y) { g_sel[i] = y; g_sel[i + 2048] = x; }
    }
    sync4(14);

    // local finish k=8192 (desc), j=1024..1
    sk[tid]        = g_sel[cbase + tid];
    sk[tid + 1024] = g_sel[cbase + tid + 1024];
    __syncthreads();
    for (int j = 1024; j > 0; j >>= 1) {
        int t = tid;
        int i = (t << 1) - (t & (j - 1));
        unsigned long long x = sk[i], y = sk[i + j];
        if (x < y) { sk[i] = y; sk[i + j] = x; }
        __syncthreads();
    }
    g_sel[cbase + tid]        = sk[tid];
    g_sel[cbase + tid + 1024] = sk[tid + 1024];
    sync4(15);

    if (b != 0) return;

    // ---- F2 (block 0): gather + NMS + output ----
    float* nx1 = (float*)dsm;
    float* ny1 = nx1 + TOPK;
    float* nx2 = nx1 + 2 * TOPK;
    float* ny2 = nx1 + 3 * TOPK;
    float* nar = nx1 + 4 * TOPK;
    unsigned* sbits = (unsigned*)(nx1 + 5 * TOPK);
    __shared__ int keepList[POSTK];

    if (tid < NBITW) sbits[tid] = 0u;
    __syncthreads();

    float rx1[6], ry1[6], rx2[6], ry2[6], rar[6];
    unsigned remloc = 0;
#pragma unroll
    for (int k6 = 0; k6 < 6; k6++) {
        int j = tid + (k6 << 10);
        if (j < TOPK) {
            unsigned long long key = g_sel[j];
            unsigned idx = 0xFFFFFFFFu - (unsigned)(key & 0xFFFFFFFFull);
            float x1 = 0.f, y1 = 0.f, x2 = 0.f, y2 = 0.f, ar = -1.f;
            if (idx < (unsigned)NANCH) {
                x1 = g_dx1[idx]; y1 = g_dy1[idx];
                x2 = g_dx2[idx]; y2 = g_dy2[idx];
                ar = g_dar[idx];
            }
            nx1[j] = x1; ny1[j] = y1; nx2[j] = x2; ny2[j] = y2; nar[j] = ar;
            rx1[k6] = x1; ry1[k6] = y1; rx2[k6] = x2; ry2[k6] = y2; rar[k6] = ar;
            if (ar < 0.f) {
                remloc |= 1u << k6;
                atomicOr(&sbits[j >> 5], 1u << (j & 31));
            }
        } else {
            remloc |= 1u << k6;
        }
    }
    if (tid == 0) atomicOr(&sbits[NBITW - 1], 0xFFFF0000u);
    __syncthreads();

    int count = 0;
    int i = 0;
    for (;;) {
        while (i < TOPK) {
            unsigned w = (~sbits[i >> 5]) & (0xFFFFFFFFu << (i & 31));
            if (w) { i = (i & ~31) + (__ffs(w) - 1); break; }
            i = (i & ~31) + 32;
        }
        if (i >= TOPK) break;
        if (tid == 0) keepList[count] = i;
        float bx1 = nx1[i], by1 = ny1[i], bx2 = nx2[i], by2 = ny2[i], ba = nar[i];
#pragma unroll
        for (int k6 = 0; k6 < 6; k6++) {
            int j = tid + (k6 << 10);
            if (j > i && !((remloc >> k6) & 1u)) {
                float xx1 = fmaxf(bx1, rx1[k6]);
                float yy1 = fmaxf(by1, ry1[k6]);
                float xx2 = fminf(bx2, rx2[k6]);
                float yy2 = fminf(by2, ry2[k6]);
                float iw = fmaxf(__fsub_rn(xx2, xx1), 0.f);
                float ih = fmaxf(__fsub_rn(yy2, yy1), 0.f);
                float inter = __fmul_rn(iw, ih);
                float denom = __fsub_rn(__fadd_rn(ba, rar[k6]), inter);
                // exact equivalent of RN(inter/denom) > 0.7f (no division)
                if ((double)inter >= MTHR * (double)denom) {
                    remloc |= 1u << k6;
                    atomicOr(&sbits[j >> 5], 1u << (j & 31));
                }
            }
        }
        count++;
        i++;
        if (count >= POSTK) break;
        __syncthreads();
    }
    __syncthreads();

    for (int t = tid; t < POSTK; t += 1024) {
        if (t < count) {
            int ii = keepList[t];
            unsigned long long key = g_sel[ii];
            unsigned u = (unsigned)(key >> 32);
            unsigned bb = (u & 0x80000000u) ? (u & 0x7FFFFFFFu) : ~u;
            float cls = __uint_as_float(bb);
            float sc = (float)(1.0 / (1.0 + exp(-(double)cls)));
            out[t * 5 + 0] = nx1[ii];
            out[t * 5 + 1] = ny1[ii];
            out[t * 5 + 2] = nx2[ii];
            out[t * 5 + 3] = ny2[ii];
            out[t * 5 + 4] = sc;
        } else {
            out[t * 5 + 0] = 0.f; out[t * 5 + 1] = 0.f; out[t * 5 + 2] = 0.f;
            out[t * 5 + 3] = 0.f; out[t * 5 + 4] = 0.f;
        }
    }
}

// ---------------- launch ----------------
extern "C" void kernel_launch(void* const* d_in, const int* in_sizes, int n_in,
                              void* d_out, int out_size)
{
    (void)in_sizes; (void)n_in; (void)out_size;
    const float* feat   = (const float*)d_in[1];
    const float* conv_w = (const float*)d_in[2];
    const float* conv_b = (const float*)d_in[3];
    const float* cls_w  = (const float*)d_in[4];
    const float* cls_b  = (const float*)d_in[5];
    const float* bbox_w = (const float*)d_in[6];
    const float* bbox_b = (const float*)d_in[7];
    float* out = (float*)d_out;

    prep_all<<<4371, 1024>>>(feat, conv_w);

    cudaFuncSetAttribute(conv_mma, cudaFuncAttributeMaxDynamicSharedMemorySize, DYNSM);
    conv_mma<<<dim3(64, 2), 512, DYNSM>>>(conv_b);

    cudaFuncSetAttribute(heads_sums, cudaFuncAttributeMaxDynamicSharedMemorySize, HSM_BYTES);
    heads_sums<<<1024, 256, HSM_BYTES>>>(cls_w, cls_b, bbox_w, bbox_b);

    cudaFuncSetAttribute(tail, cudaFuncAttributeMaxDynamicSharedMemorySize, TAILSM);
    tail<<<GRIDT, 1024, TAILSM>>>(out);
}

// round 13
// speedup vs baseline: 4.3093x; 4.3093x over previous
#include <cuda_runtime.h>
#include <cuda_fp16.h>
#include <cstdint>
#include <math.h>

// ---------------- problem constants ----------------
#define HW      16384
#define CH      256
#define NANCH   147456
#define TOPK    6000
#define POSTK   300
#define STRIDE  8.0f
#define IMSZ    1024.0f
#define DWCLIP  4.135166556742356f
#define NMSTHR  0.7f
#define MINSZ   16.0f

#define PADW    132
#define PADH    130
#define PADHW   (PADW*PADH)

#define NSEL    8192
#define NBITW   188

// conv tiling (unchanged, passing)
#define NSTAGE  36
#define RSB     144
#define RSW     36
#define A_SEC   18432
#define B_SEC   36864
#define BUFB    (2*A_SEC + 2*B_SEC)
#define DYNSM   (2*BUFB)

// tail
#define GRIDT   148
#define TAILSM  121088      // boxes float4[6000]+area[6000]=120000 + removed 752

// ---------------- scratch ----------------
__device__ float g_rpnfeat[CH * HW];
__device__ __align__(256) __half g_tb[2 * PADHW * 256];
__device__ __align__(256) __half g_wa[2 * 9 * 256 * 256];
__device__ float g_boxes[NANCH * 4];            // raw deltas + bias
__device__ unsigned long long g_keys[NANCH];
__device__ unsigned long long g_sel[NSEL];
__device__ float g_dx1[NANCH], g_dy1[NANCH], g_dx2[NANCH], g_dy2[NANCH], g_dar[NANCH];
__device__ float4 g_obx[TOPK];                  // ordered (sorted) boxes
__device__ float g_oar[TOPK];                   // ordered areas (-1 = invalid)
__device__ unsigned g_mat[TOPK * NBITW];        // suppression matrix (4.5 MB)
__device__ int g_hist1[4096];
__device__ int g_hist2[4096];
__device__ int g_B1;
__device__ int g_cntgt;
__device__ unsigned g_T;
__device__ int g_selcnt;
__device__ int g_bars[64];

// ---------------- helpers ----------------
__device__ __forceinline__ uint32_t smem_u32(const void* p) {
    uint32_t a;
    asm("{ .reg .u64 t; cvta.to.shared.u64 t, %1; cvt.u32.u64 %0, t; }" : "=r"(a) : "l"(p));
    return a;
}
#define CP_ASYNC16(dst, src) \
    asm volatile("cp.async.cg.shared.global [%0], [%1], 16;" :: "r"(dst), "l"(src))
#define CP_COMMIT()  asm volatile("cp.async.commit_group;" ::: "memory")
#define CP_WAIT0()   asm volatile("cp.async.wait_group 0;" ::: "memory")

#define MMA16816(d, a, b) \
    asm volatile("mma.sync.aligned.m16n8k16.row.col.f32.f16.f16.f32 " \
        "{%0,%1,%2,%3}, {%4,%5,%6,%7}, {%8,%9}, {%0,%1,%2,%3};" \
        : "+f"((d)[0]), "+f"((d)[1]), "+f"((d)[2]), "+f"((d)[3]) \
        : "r"((a)[0]), "r"((a)[1]), "r"((a)[2]), "r"((a)[3]), "r"((b)[0]), "r"((b)[1]))

__device__ __forceinline__ void gsync(int k) {
    __threadfence();
    __syncthreads();
    if (threadIdx.x == 0) {
        atomicAdd(&g_bars[k], 1);
        while (atomicAdd(&g_bars[k], 0) < GRIDT) { __nanosleep(64); }
    }
    __syncthreads();
}
__device__ __forceinline__ void sync4(int k) {
    __threadfence();
    __syncthreads();
    if (threadIdx.x == 0) {
        atomicAdd(&g_bars[k], 1);
        while (atomicAdd(&g_bars[k], 0) < 4) { __nanosleep(32); }
    }
    __syncthreads();
}

// =====================================================================
// fused prep (unchanged, passing)
// =====================================================================
__global__ __launch_bounds__(1024)
void prep_all(const float* __restrict__ feat, const float* __restrict__ w)
{
    __shared__ float sm[32][33];
    const int b = blockIdx.x;
    const int tid = threadIdx.x;

    if (b < 4096) {
        const int px0 = (b & 511) << 5;
        const int ic0 = (b >> 9) << 5;
        const int tx = tid & 31, ty = tid >> 5;
        sm[ty][tx] = feat[(ic0 + ty) * HW + px0 + tx];
        __syncthreads();
        float v = sm[tx][ty];
        __half h0 = __float2half_rn(v);
        __half h1 = __float2half_rn(v - __half2float(h0));
        const int p = px0 + ty;
        const int padpos = ((p >> 7) + 1) * PADW + (p & 127) + 1;
        const int waddr = padpos * 256 + ic0 + tx;
        g_tb[waddr] = h0;
        g_tb[PADHW * 256 + waddr] = h1;
    } else if (b < 4160) {
        int idx = (b - 4096) * 1024 + tid;
        int oc = idx >> 8, ic = idx & 255;
#pragma unroll
        for (int tap = 0; tap < 9; tap++) {
            float x = w[oc * 2304 + ic * 9 + tap];
            __half h0 = __float2half_rn(x);
            __half h1 = __float2half_rn(x - __half2float(h0));
            int base = (tap * 256 + oc) * 256 + ic;
            g_wa[base] = h0;
            g_wa[9 * 65536 + base] = h1;
        }
    } else if (b < 4354) {
        int gid = (b - 4160) * 1024 + tid;
        if (gid < 776 * 256) {
            int hid = gid >> 8, ic = gid & 255;
            int yp, xp;
            if (hid < 132)      { yp = 0;   xp = hid; }
            else if (hid < 264) { yp = 129; xp = hid - 132; }
            else {
                int r = hid - 264;
                yp = 1 + (r >> 2);
                int c = r & 3;
                xp = (c == 0) ? 0 : 128 + c;
            }
            int base = (yp * PADW + xp) * 256 + ic;
            g_tb[base] = __float2half_rn(0.f);
            g_tb[PADHW * 256 + base] = __float2half_rn(0.f);
        }
    } else {
        int gid = (b - 4354) * 1024 + tid;
        if (gid < 4096) g_hist1[gid] = 0;
        else if (gid < 8192) g_hist2[gid - 4096] = 0;
        else if (gid < 16384) g_sel[gid - 8192] = 0ull;
        else if (gid < 16448) g_bars[gid - 16384] = 0;
        else if (gid == 16448) g_selcnt = 0;
        else if (gid == 16449) g_B1 = 0;
        else if (gid == 16450) g_cntgt = 0;
        else if (gid == 16451) g_T = 0u;
    }
}

// =====================================================================
// conv (unchanged, passing)
// =====================================================================
__device__ __forceinline__ void issue_stage(uint32_t sbase, int s, int tid, int yblk, int oc0)
{
    const int tap = s >> 2;
    const int icb = (s & 3) << 7;
    const int ky = tap / 3, kx = tap - ky * 3;
#pragma unroll
    for (int i = 0; i < 12; i++) {
        int cid = tid + (i << 9);
        int row = cid >> 3, c = cid & 7;
        const char* src;
        uint32_t dst;
        if (row < 256) {
            int sp = row >> 7, r = row & 127;
            src = (const char*)g_wa + ((sp * 9 + tap) * 256 + oc0 + r) * 512 + icb;
            dst = sbase + sp * A_SEC + r * RSB;
        } else {
            int rowb = row - 256;
            int sp = rowb >> 8, p = rowb & 255;
            int yy = (yblk << 1) + (p >> 7) + ky;
            int xx = (p & 127) + kx;
            src = (const char*)g_tb + (sp * PADHW + yy * PADW + xx) * 512 + icb;
            dst = sbase + 2 * A_SEC + sp * B_SEC + p * RSB;
        }
        CP_ASYNC16(dst + c * 16, src + c * 16);
    }
    CP_COMMIT();
}

__global__ void __launch_bounds__(512, 1) conv_mma(const float* __restrict__ bias)
{
    extern __shared__ char dsm[];
    const uint32_t smem_base = smem_u32(dsm);
    const int tid = threadIdx.x;
    const int yblk = blockIdx.x;
    const int oc0 = blockIdx.y << 7;
    const int wid = tid >> 5, lane = tid & 31;
    const int wm = wid & 3, wn = wid >> 2;
    const int g = lane >> 2, t = lane & 3;

    float acc[2][8][4];
#pragma unroll
    for (int mt = 0; mt < 2; mt++)
#pragma unroll
        for (int nt = 0; nt < 8; nt++)
#pragma unroll
            for (int c = 0; c < 4; c++) acc[mt][nt][c] = 0.f;

    issue_stage(smem_base, 0, tid, yblk, oc0);
    CP_WAIT0();
    __syncthreads();

    for (int s = 0; s < NSTAGE; s++) {
        if (s + 1 < NSTAGE)
            issue_stage(smem_base + ((s + 1) & 1) * BUFB, s + 1, tid, yblk, oc0);

        const uint32_t* smw = (const uint32_t*)(dsm + (s & 1) * BUFB);
#pragma unroll
        for (int k16 = 0; k16 < 4; k16++) {
            const int ko = k16 * 8 + t;
            uint32_t af[2][2][4];
#pragma unroll
            for (int sp = 0; sp < 2; sp++)
#pragma unroll
                for (int mt = 0; mt < 2; mt++) {
                    int row = wm * 32 + mt * 16 + g;
                    int base = sp * (A_SEC / 4) + row * RSW + ko;
                    af[sp][mt][0] = smw[base];
                    af[sp][mt][1] = smw[base + 8 * RSW];
                    af[sp][mt][2] = smw[base + 4];
                    af[sp][mt][3] = smw[base + 8 * RSW + 4];
                }
#pragma unroll
            for (int sb = 0; sb < 2; sb++) {
                uint32_t bf_[8][2];
#pragma unroll
                for (int nt = 0; nt < 8; nt++) {
                    int n = wn * 64 + nt * 8 + g;
                    int base = 2 * (A_SEC / 4) + sb * (B_SEC / 4) + n * RSW + ko;
                    bf_[nt][0] = smw[base];
                    bf_[nt][1] = smw[base + 4];
                }
                const int nsa = (sb == 0) ? 2 : 1;
#pragma unroll
                for (int sa = 0; sa < 2; sa++) {
                    if (sa < nsa) {
#pragma unroll
                        for (int mt = 0; mt < 2; mt++)
#pragma unroll
                            for (int nt = 0; nt < 8; nt++)
                                MMA16816(acc[mt][nt], af[sa][mt], bf_[nt]);
                    }
                }
            }
        }

        if (s + 1 < NSTAGE) {
            CP_WAIT0();
            __syncthreads();
        }
    }

#pragma unroll
    for (int mt = 0; mt < 2; mt++) {
        int ocl = oc0 + wm * 32 + mt * 16 + g;
        float b0 = bias[ocl];
        float b1 = bias[ocl + 8];
#pragma unroll
        for (int nt = 0; nt < 8; nt++) {
            int col = wn * 64 + nt * 8 + 2 * t;
            float2 lo, hi;
            lo.x = fmaxf(acc[mt][nt][0] + b0, 0.f);
            lo.y = fmaxf(acc[mt][nt][1] + b0, 0.f);
            hi.x = fmaxf(acc[mt][nt][2] + b1, 0.f);
            hi.y = fmaxf(acc[mt][nt][3] + b1, 0.f);
            *(float2*)&g_rpnfeat[ocl * HW + yblk * 256 + col] = lo;
            *(float2*)&g_rpnfeat[(ocl + 8) * HW + yblk * 256 + col] = hi;
        }
    }
}

// =====================================================================
// heads (unchanged, passing)
// =====================================================================
#define HSM_FLOATS (11520 + 720)
#define HSM_BYTES  (HSM_FLOATS * 4)

__global__ __launch_bounds__(256)
void heads_sums(const float* __restrict__ cls_w, const float* __restrict__ cls_b,
                const float* __restrict__ bbox_w, const float* __restrict__ bbox_b)
{
    extern __shared__ float hsm[];
    float* ws   = hsm;
    float* red  = hsm;
    float* sums = hsm + 11520;

    const int tid = threadIdx.x;
    for (int i = tid; i < 9 * 256; i += 256)  ws[(i >> 8) * 256 + (i & 255)] = cls_w[i];
    for (int i = tid; i < 36 * 256; i += 256) ws[(9 + (i >> 8)) * 256 + (i & 255)] = bbox_w[i];
    __syncthreads();

    const int pl = tid & 15;
    const int q  = tid >> 4;
    const int p  = (blockIdx.x << 4) + pl;

    float acc[45];
#pragma unroll
    for (int j = 0; j < 45; j++) acc[j] = 0.f;

    const float* rf = g_rpnfeat + (q << 4) * HW + p;
    const float* wq = ws + (q << 4);
#pragma unroll
    for (int cc = 0; cc < 16; cc++) {
        float v = rf[cc * HW];
#pragma unroll
        for (int j = 0; j < 45; j++) acc[j] = fmaf(wq[j * 256 + cc], v, acc[j]);
    }
    __syncthreads();

    {
        float* r = red + (q * 16 + pl) * 45;
#pragma unroll
        for (int j = 0; j < 45; j++) r[j] = acc[j];
    }
    __syncthreads();

    for (int task = tid; task < 720; task += 256) {
        int pl2 = task / 45, j = task - pl2 * 45;
        float s = 0.f;
#pragma unroll
        for (int q2 = 0; q2 < 16; q2++)
            s += red[(q2 * 16 + pl2) * 45 + j];
        sums[pl2 * 45 + j] = s;
    }
    __syncthreads();

    if (tid < 144) {
        int pxl = tid / 9;
        int a   = tid - pxl * 9;
        const float* s = sums + pxl * 45;
        int pg = (blockIdx.x << 4) + pxl;
        int idx = pg * 9 + a;

        g_boxes[idx * 4 + 0] = s[9 + a * 4 + 0] + bbox_b[a * 4 + 0];
        g_boxes[idx * 4 + 1] = s[9 + a * 4 + 1] + bbox_b[a * 4 + 1];
        g_boxes[idx * 4 + 2] = s[9 + a * 4 + 2] + bbox_b[a * 4 + 2];
        g_boxes[idx * 4 + 3] = s[9 + a * 4 + 3] + bbox_b[a * 4 + 3];

        float cls = s[a] + cls_b[a];
        unsigned bb = __float_as_uint(cls);
        unsigned u = (bb & 0x80000000u) ? ~bb : (bb | 0x80000000u);
        g_keys[idx] = ((unsigned long long)u << 32) | (unsigned)(0xFFFFFFFFu - (unsigned)idx);
    }
}

// =====================================================================
// TAIL: select -> decode -> sort -> PARALLEL suppression matrix -> greedy
// =====================================================================
__device__ void scan_phase(int* s, const int* h, int base, int phase)
{
    const int t = threadIdx.x;
    int c0 = h[4 * t], c1 = h[4 * t + 1], c2 = h[4 * t + 2], c3 = h[4 * t + 3];
    int v = c0 + c1 + c2 + c3;
    s[t] = v;
    __syncthreads();
    for (int off = 1; off < 1024; off <<= 1) {
        int add = (t + off < 1024) ? s[t + off] : 0;
        __syncthreads();
        v += add;
        s[t] = v;
        __syncthreads();
    }
    int suff = s[t];
    int above = (t < 1023) ? s[t + 1] : 0;
    if (base + above < TOPK && base + suff >= TOPK) {
        int cum = base + above;
        int c[4] = {c0, c1, c2, c3};
#pragma unroll
        for (int b = 3; b >= 0; b--) {
            if (cum + c[b] >= TOPK) {
                if (phase == 0) { g_B1 = 4 * t + b; g_cntgt = cum; }
                else            { g_T = ((unsigned)g_B1 << 12) | (unsigned)(4 * t + b); }
                break;
            }
            cum += c[b];
        }
    }
    __syncthreads();
}

__global__ __launch_bounds__(1024)
void tail(float* __restrict__ out)
{
    extern __shared__ char dsm[];
    const int tid = threadIdx.x;
    const int b = blockIdx.x;

    // ---- A: hist1 ----
    {
        int* h = (int*)dsm;
        for (int i = tid; i < 4096; i += 1024) h[i] = 0;
        __syncthreads();
        for (int i = b * 1024 + tid; i < NANCH; i += GRIDT * 1024)
            atomicAdd(&h[(unsigned)(g_keys[i] >> 52)], 1);
        __syncthreads();
        for (int i = tid; i < 4096; i += 1024) {
            int v = h[i];
            if (v) atomicAdd(&g_hist1[i], v);
        }
    }
    gsync(0);
    if (b == 0) scan_phase((int*)dsm, g_hist1, 0, 0);
    gsync(1);
    {
        const unsigned b1 = (unsigned)(*(volatile int*)&g_B1);
        int* h = (int*)dsm;
        for (int i = tid; i < 4096; i += 1024) h[i] = 0;
        __syncthreads();
        for (int i = b * 1024 + tid; i < NANCH; i += GRIDT * 1024) {
            unsigned long long key = g_keys[i];
            if ((unsigned)(key >> 52) == b1)
                atomicAdd(&h[(unsigned)((key >> 40) & 0xFFFull)], 1);
        }
        __syncthreads();
        for (int i = tid; i < 4096; i += 1024) {
            int v = h[i];
            if (v) atomicAdd(&g_hist2[i], v);
        }
    }
    gsync(2);
    if (b == 0) scan_phase((int*)dsm, g_hist2, *(volatile int*)&g_cntgt, 1);
    gsync(3);

    // ---- E: compact + parallel decode ----
    {
        const float AR[3]  = {0.5f, 1.0f, 2.0f};
        const float SCL[3] = {128.f, 256.f, 512.f};
        const unsigned T = *(volatile unsigned*)&g_T;
        for (int i = b * 1024 + tid; i < NANCH; i += GRIDT * 1024) {
            unsigned long long key = g_keys[i];
            if ((unsigned)(key >> 40) >= T) {
                int p = atomicAdd(&g_selcnt, 1);
                if (p < NSEL) g_sel[p] = key;

                float4 d = *(const float4*)&g_boxes[i * 4];
                int pg = i / 9;
                int a = i - pg * 9;
                float sx = (float)(pg & 127) * STRIDE;
                float sy = (float)(pg >> 7) * STRIDE;
                int ia = a / 3, is_ = a - ia * 3;
                float hr  = sqrtf(AR[ia]);
                float wr  = __frcp_rn(hr);
                float hsv = __fmul_rn(hr, SCL[is_]);
                float wsv = __fmul_rn(wr, SCL[is_]);
                float bx1 = rintf(__fmul_rn(-wsv, 0.5f));
                float by1 = rintf(__fmul_rn(-hsv, 0.5f));
                float bx2 = rintf(__fmul_rn(wsv, 0.5f));
                float by2 = rintf(__fmul_rn(hsv, 0.5f));
                float ax1 = __fadd_rn(sx, bx1), ay1 = __fadd_rn(sy, by1);
                float ax2 = __fadd_rn(sx, bx2), ay2 = __fadd_rn(sy, by2);
                float aw = __fsub_rn(ax2, ax1), ah = __fsub_rn(ay2, ay1);
                float cx = __fadd_rn(ax1, __fmul_rn(0.5f, aw));
                float cy = __fadd_rn(ay1, __fmul_rn(0.5f, ah));

                float dw = fminf(d.z, DWCLIP);
                float dh = fminf(d.w, DWCLIP);
                float px = __fadd_rn(__fmul_rn(d.x, aw), cx);
                float py = __fadd_rn(__fmul_rn(d.y, ah), cy);
                float pw = __fmul_rn((float)exp((double)dw), aw);
                float ph = __fmul_rn((float)exp((double)dh), ah);

                float x1 = __fsub_rn(px, __fmul_rn(0.5f, pw));
                float y1 = __fsub_rn(py, __fmul_rn(0.5f, ph));
                float x2 = __fadd_rn(px, __fmul_rn(0.5f, pw));
                float y2 = __fadd_rn(py, __fmul_rn(0.5f, ph));

                x1 = fminf(fmaxf(x1, 0.f), IMSZ);
                y1 = fminf(fmaxf(y1, 0.f), IMSZ);
                x2 = fminf(fmaxf(x2, 0.f), IMSZ);
                y2 = fminf(fmaxf(y2, 0.f), IMSZ);
                float wv = __fsub_rn(x2, x1);
                float hv = __fsub_rn(y2, y1);
                float ar = __fmul_rn(wv, hv);
                if (!(wv >= MINSZ && hv >= MINSZ)) ar = -1.f;

                g_dx1[i] = x1; g_dy1[i] = y1; g_dx2[i] = x2; g_dy2[i] = y2; g_dar[i] = ar;
            }
        }
    }
    gsync(4);

    // ---- F1: parallel sort on blocks 0-3 (blocks >=4 skip to gsync(5)) ----
    if (b < 4) {
        unsigned long long* sk = (unsigned long long*)dsm;
        const int cbase = b << 11;

        sk[tid]        = g_sel[cbase + tid];
        sk[tid + 1024] = g_sel[cbase + tid + 1024];
        __syncthreads();
        for (int k = 2; k <= 2048; k <<= 1) {
            for (int j = k >> 1; j > 0; j >>= 1) {
                int t = tid;
                int i = (t << 1) - (t & (j - 1));
                bool desc = (((cbase + i) & k) == 0);
                unsigned long long x = sk[i], y = sk[i + j];
                if ((x < y) == desc) { sk[i] = y; sk[i + j] = x; }
                __syncthreads();
            }
        }
        g_sel[cbase + tid]        = sk[tid];
        g_sel[cbase + tid + 1024] = sk[tid + 1024];
        sync4(10);

        {
            int t4 = (b << 10) + tid;
            int i = (t4 << 1) - (t4 & 2047);
            bool desc = ((i & 4096) == 0);
            unsigned long long x = g_sel[i], y = g_sel[i + 2048];
            if ((x < y) == desc) { g_sel[i] = y; g_sel[i + 2048] = x; }
        }
        sync4(11);

        sk[tid]        = g_sel[cbase + tid];
        sk[tid + 1024] = g_sel[cbase + tid + 1024];
        __syncthreads();
        for (int j = 1024; j > 0; j >>= 1) {
            int t = tid;
            int i = (t << 1) - (t & (j - 1));
            bool desc = (((cbase + i) & 4096) == 0);
            unsigned long long x = sk[i], y = sk[i + j];
            if ((x < y) == desc) { sk[i] = y; sk[i + j] = x; }
            __syncthreads();
        }
        g_sel[cbase + tid]        = sk[tid];
        g_sel[cbase + tid + 1024] = sk[tid + 1024];
        sync4(12);

        {
            int t4 = (b << 10) + tid;
            unsigned long long x = g_sel[t4], y = g_sel[t4 + 4096];
            if (x < y) { g_sel[t4] = y; g_sel[t4 + 4096] = x; }
        }
        sync4(13);

        {
            int t4 = (b << 10) + tid;
            int i = (t4 << 1) - (t4 & 2047);
            unsigned long long x = g_sel[i], y = g_sel[i + 2048];
            if (x < y) { g_sel[i] = y; g_sel[i + 2048] = x; }
        }
        sync4(14);

        sk[tid]        = g_sel[cbase + tid];
        sk[tid + 1024] = g_sel[cbase + tid + 1024];
        __syncthreads();
        for (int j = 1024; j > 0; j >>= 1) {
            int t = tid;
            int i = (t << 1) - (t & (j - 1));
            unsigned long long x = sk[i], y = sk[i + j];
            if (x < y) { sk[i] = y; sk[i + j] = x; }
            __syncthreads();
        }
        g_sel[cbase + tid]        = sk[tid];
        g_sel[cbase + tid + 1024] = sk[tid + 1024];
    }
    gsync(5);

    // ---- G: ordered box arrays (all blocks; <=1 task per thread) ----
    for (int j = b * 1024 + tid; j < TOPK; j += GRIDT * 1024) {
        unsigned long long key = g_sel[j];
        unsigned idx = 0xFFFFFFFFu - (unsigned)(key & 0xFFFFFFFFull);
        float4 bx = make_float4(0.f, 0.f, 0.f, 0.f);
        float ar = -1.f;
        if (idx < (unsigned)NANCH) {
            bx = make_float4(g_dx1[idx], g_dy1[idx], g_dx2[idx], g_dy2[idx]);
            ar = g_dar[idx];
        }
        g_obx[j] = bx;
        g_oar[j] = ar;
    }
    gsync(6);

    // ---- H: parallel suppression matrix (all blocks) ----
    float4* sb4 = (float4*)dsm;                       // 96000 B
    float* sar2 = (float*)(dsm + 96000);              // 24000 B
    for (int j = tid; j < TOPK; j += 1024) {
        sb4[j] = g_obx[j];
        sar2[j] = g_oar[j];
    }
    __syncthreads();

    for (int task = b * 1024 + tid; task < TOPK * NBITW; task += GRIDT * 1024) {
        int r = task / NBITW;
        int w = task - r * NBITW;
        float4 bi = sb4[r];
        float ai = sar2[r];
        unsigned bits = 0u;
        int j0 = w << 5;
        int jend = min(j0 + 32, TOPK);
#pragma unroll 4
        for (int j = (j0 > r + 1 ? j0 : r + 1); j < jend; j++) {
            float4 bj = sb4[j];
            float xx1 = fmaxf(bi.x, bj.x);
            float yy1 = fmaxf(bi.y, bj.y);
            float xx2 = fminf(bi.z, bj.z);
            float yy2 = fminf(bi.w, bj.w);
            float iw = fmaxf(__fsub_rn(xx2, xx1), 0.f);
            float ih = fmaxf(__fsub_rn(yy2, yy1), 0.f);
            float inter = __fmul_rn(iw, ih);
            float denom = __fsub_rn(__fadd_rn(ai, sar2[j]), inter);
            if (__fdiv_rn(inter, denom) > NMSTHR) bits |= 1u << (j - j0);
        }
        g_mat[task] = bits;
    }

    // arrive at barrier 7; only block 0 continues
    __threadfence();
    __syncthreads();
    if (tid == 0) atomicAdd(&g_bars[7], 1);
    if (b != 0) return;
    if (tid == 0) { while (atomicAdd(&g_bars[7], 0) < GRIDT) { __nanosleep(64); } }
    __syncthreads();

    // ---- I (block 0): greedy reduction over bitmap + output ----
    unsigned* removed = (unsigned*)(dsm + 120064);    // 752 B, after boxes
    __shared__ int keepList[POSTK];
    {
        const int warpid = tid >> 5, lane = tid & 31;
#pragma unroll
        for (int q = 0; q < 6; q++) {
            int wd = q * 32 + warpid;
            if (wd < NBITW) {
                int j = (wd << 5) + lane;
                bool bad = (j >= TOPK) || (sar2[j] < 0.f);
                unsigned m = __ballot_sync(0xFFFFFFFFu, bad);
                if (lane == 0) removed[wd] = m;
            }
        }
    }
    __syncthreads();

    int count = 0;
    int i = 0;
    for (;;) {
        while (i < TOPK) {
            unsigned wv = (~removed[i >> 5]) & (0xFFFFFFFFu << (i & 31));
            if (wv) { i = (i & ~31) + (__ffs(wv) - 1); break; }
            i = (i & ~31) + 32;
        }
        if (i >= TOPK) break;
        if (tid == 0) keepList[count] = i;
        count++;
        if (count >= POSTK) break;
        if (tid < NBITW) removed[tid] |= g_mat[i * NBITW + tid];
        i++;
        __syncthreads();
    }
    __syncthreads();

    for (int t = tid; t < POSTK; t += 1024) {
        if (t < count) {
            int ii = keepList[t];
            float4 bb4 = sb4[ii];
            unsigned long long key = g_sel[ii];
            unsigned u = (unsigned)(key >> 32);
            unsigned bb = (u & 0x80000000u) ? (u & 0x7FFFFFFFu) : ~u;
            float cls = __uint_as_float(bb);
            float sc = (float)(1.0 / (1.0 + exp(-(double)cls)));
            out[t * 5 + 0] = bb4.x;
            out[t * 5 + 1] = bb4.y;
            out[t * 5 + 2] = bb4.z;
            out[t * 5 + 3] = bb4.w;
            out[t * 5 + 4] = sc;
        } else {
            out[t * 5 + 0] = 0.f; out[t * 5 + 1] = 0.f; out[t * 5 + 2] = 0.f;
            out[t * 5 + 3] = 0.f; out[t * 5 + 4] = 0.f;
        }
    }
}

// ---------------- launch ----------------
extern "C" void kernel_launch(void* const* d_in, const int* in_sizes, int n_in,
                              void* d_out, int out_size)
{
    (void)in_sizes; (void)n_in; (void)out_size;
    const float* feat   = (const float*)d_in[1];
    const float* conv_w = (const float*)d_in[2];
    const float* conv_b = (const float*)d_in[3];
    const float* cls_w  = (const float*)d_in[4];
    const float* cls_b  = (const float*)d_in[5];
    const float* bbox_w = (const float*)d_in[6];
    const float* bbox_b = (const float*)d_in[7];
    float* out = (float*)d_out;

    prep_all<<<4371, 1024>>>(feat, conv_w);

    cudaFuncSetAttribute(conv_mma, cudaFuncAttributeMaxDynamicSharedMemorySize, DYNSM);
    conv_mma<<<dim3(64, 2), 512, DYNSM>>>(conv_b);

    cudaFuncSetAttribute(heads_sums, cudaFuncAttributeMaxDynamicSharedMemorySize, HSM_BYTES);
    heads_sums<<<1024, 256, HSM_BYTES>>>(cls_w, cls_b, bbox_w, bbox_b);

    cudaFuncSetAttribute(tail, cudaFuncAttributeMaxDynamicSharedMemorySize, TAILSM);
    tail<<<GRIDT, 1024, TAILSM>>>(out);
}

// round 14
// speedup vs baseline: 5.2419x; 1.2164x over previous
#include <cuda_runtime.h>
#include <cuda_fp16.h>
#include <cstdint>
#include <math.h>

// ---------------- problem constants ----------------
#define HW      16384
#define CH      256
#define NANCH   147456
#define TOPK    6000
#define POSTK   300
#define STRIDE  8.0f
#define IMSZ    1024.0f
#define DWCLIP  4.135166556742356f
#define NMSTHR  0.7f
#define MINSZ   16.0f
#define MTHR    0x1.666667p-1    // midpoint(0.7f, nextafterf(0.7f)), exact in double

#define PADW    132
#define PADH    130
#define PADHW   (PADW*PADH)

#define NSEL    8192
#define NBITW   188
#define CHUNK   512              // matrix rows per chunk
#define NCHUNK  12               // ceil(6000/512)

// conv tiling (unchanged, passing)
#define NSTAGE  36
#define RSB     144
#define RSW     36
#define A_SEC   18432
#define B_SEC   36864
#define BUFB    (2*A_SEC + 2*B_SEC)
#define DYNSM   (2*BUFB)

// tail
#define GRIDT   148
#define TAILSM  121088

// ---------------- scratch ----------------
__device__ float g_rpnfeat[CH * HW];
__device__ __align__(256) __half g_tb[2 * PADHW * 256];
__device__ __align__(256) __half g_wa[2 * 9 * 256 * 256];
__device__ float g_boxes[NANCH * 4];
__device__ unsigned long long g_keys[NANCH];
__device__ unsigned long long g_sel[NSEL];
__device__ float g_dx1[NANCH], g_dy1[NANCH], g_dx2[NANCH], g_dy2[NANCH], g_dar[NANCH];
__device__ float4 g_obx[TOPK];
__device__ float g_oar[TOPK];
__device__ unsigned g_mat[TOPK * NBITW];
__device__ int g_hist1[4096];
__device__ int g_hist2[4096];
__device__ int g_B1;
__device__ int g_cntgt;
__device__ unsigned g_T;
__device__ int g_selcnt;
__device__ int g_work;
__device__ int g_bars[64];

// ---------------- helpers ----------------
__device__ __forceinline__ uint32_t smem_u32(const void* p) {
    uint32_t a;
    asm("{ .reg .u64 t; cvta.to.shared.u64 t, %1; cvt.u32.u64 %0, t; }" : "=r"(a) : "l"(p));
    return a;
}
#define CP_ASYNC16(dst, src) \
    asm volatile("cp.async.cg.shared.global [%0], [%1], 16;" :: "r"(dst), "l"(src))
#define CP_COMMIT()  asm volatile("cp.async.commit_group;" ::: "memory")
#define CP_WAIT0()   asm volatile("cp.async.wait_group 0;" ::: "memory")

#define MMA16816(d, a, b) \
    asm volatile("mma.sync.aligned.m16n8k16.row.col.f32.f16.f16.f32 " \
        "{%0,%1,%2,%3}, {%4,%5,%6,%7}, {%8,%9}, {%0,%1,%2,%3};" \
        : "+f"((d)[0]), "+f"((d)[1]), "+f"((d)[2]), "+f"((d)[3]) \
        : "r"((a)[0]), "r"((a)[1]), "r"((a)[2]), "r"((a)[3]), "r"((b)[0]), "r"((b)[1]))

__device__ __forceinline__ void gsync(int k) {
    __threadfence();
    __syncthreads();
    if (threadIdx.x == 0) {
        atomicAdd(&g_bars[k], 1);
        while (atomicAdd(&g_bars[k], 0) < GRIDT) { __nanosleep(64); }
    }
    __syncthreads();
}
__device__ __forceinline__ void sync4(int k) {
    __threadfence();
    __syncthreads();
    if (threadIdx.x == 0) {
        atomicAdd(&g_bars[k], 1);
        while (atomicAdd(&g_bars[k], 0) < 4) { __nanosleep(32); }
    }
    __syncthreads();
}

// exact-decision IoU suppression test (bit-identical to RN(inter/denom) > 0.7f)
__device__ __forceinline__ bool iou_sup(float4 bi, float ai, float4 bj, float aj) {
    float xx1 = fmaxf(bi.x, bj.x);
    float yy1 = fmaxf(bi.y, bj.y);
    float xx2 = fminf(bi.z, bj.z);
    float yy2 = fminf(bi.w, bj.w);
    float iw = fmaxf(__fsub_rn(xx2, xx1), 0.f);
    float ih = fmaxf(__fsub_rn(yy2, yy1), 0.f);
    float inter = __fmul_rn(iw, ih);
    float denom = __fsub_rn(__fadd_rn(ai, aj), inter);
    float lo = __fmul_rn(0.699f, denom);
    float hi = __fmul_rn(0.701f, denom);
    if (inter <= lo) return false;
    if (inter >= hi) return true;
    return (double)inter >= MTHR * (double)denom;     // exact midpoint compare
}

// compute suppression-matrix rows [r0, r1) with grid-stride (gidx, gstride)
__device__ void mat_rows(const float4* sb4, const float* sar2, int r0, int r1,
                         int gidx, int gstride)
{
    for (int task = r0 * NBITW + gidx; task < r1 * NBITW; task += gstride) {
        int r = task / NBITW;
        int w = task - r * NBITW;
        float4 bi = sb4[r];
        float ai = sar2[r];
        unsigned bits = 0u;
        int j0 = w << 5;
        int jend = min(j0 + 32, TOPK);
        for (int j = (j0 > r + 1 ? j0 : r + 1); j < jend; j++) {
            if (iou_sup(bi, ai, sb4[j], sar2[j])) bits |= 1u << (j - j0);
        }
        g_mat[task] = bits;
    }
}

// =====================================================================
// fused prep (R13 + g_work reset)
// =====================================================================
__global__ __launch_bounds__(1024)
void prep_all(const float* __restrict__ feat, const float* __restrict__ w)
{
    __shared__ float sm[32][33];
    const int b = blockIdx.x;
    const int tid = threadIdx.x;

    if (b < 4096) {
        const int px0 = (b & 511) << 5;
        const int ic0 = (b >> 9) << 5;
        const int tx = tid & 31, ty = tid >> 5;
        sm[ty][tx] = feat[(ic0 + ty) * HW + px0 + tx];
        __syncthreads();
        float v = sm[tx][ty];
        __half h0 = __float2half_rn(v);
        __half h1 = __float2half_rn(v - __half2float(h0));
        const int p = px0 + ty;
        const int padpos = ((p >> 7) + 1) * PADW + (p & 127) + 1;
        const int waddr = padpos * 256 + ic0 + tx;
        g_tb[waddr] = h0;
        g_tb[PADHW * 256 + waddr] = h1;
    } else if (b < 4160) {
        int idx = (b - 4096) * 1024 + tid;
        int oc = idx >> 8, ic = idx & 255;
#pragma unroll
        for (int tap = 0; tap < 9; tap++) {
            float x = w[oc * 2304 + ic * 9 + tap];
            __half h0 = __float2half_rn(x);
            __half h1 = __float2half_rn(x - __half2float(h0));
            int base = (tap * 256 + oc) * 256 + ic;
            g_wa[base] = h0;
            g_wa[9 * 65536 + base] = h1;
        }
    } else if (b < 4354) {
        int gid = (b - 4160) * 1024 + tid;
        if (gid < 776 * 256) {
            int hid = gid >> 8, ic = gid & 255;
            int yp, xp;
            if (hid < 132)      { yp = 0;   xp = hid; }
            else if (hid < 264) { yp = 129; xp = hid - 132; }
            else {
                int r = hid - 264;
                yp = 1 + (r >> 2);
                int c = r & 3;
                xp = (c == 0) ? 0 : 128 + c;
            }
            int base = (yp * PADW + xp) * 256 + ic;
            g_tb[base] = __float2half_rn(0.f);
            g_tb[PADHW * 256 + base] = __float2half_rn(0.f);
        }
    } else {
        int gid = (b - 4354) * 1024 + tid;
        if (gid < 4096) g_hist1[gid] = 0;
        else if (gid < 8192) g_hist2[gid - 4096] = 0;
        else if (gid < 16384) g_sel[gid - 8192] = 0ull;
        else if (gid < 16448) g_bars[gid - 16384] = 0;
        else if (gid == 16448) g_selcnt = 0;
        else if (gid == 16449) g_B1 = 0;
        else if (gid == 16450) g_cntgt = 0;
        else if (gid == 16451) g_T = 0u;
        else if (gid == 16452) g_work = 0;
    }
}

// =====================================================================
// conv (unchanged, passing)
// =====================================================================
__device__ __forceinline__ void issue_stage(uint32_t sbase, int s, int tid, int yblk, int oc0)
{
    const int tap = s >> 2;
    const int icb = (s & 3) << 7;
    const int ky = tap / 3, kx = tap - ky * 3;
#pragma unroll
    for (int i = 0; i < 12; i++) {
        int cid = tid + (i << 9);
        int row = cid >> 3, c = cid & 7;
        const char* src;
        uint32_t dst;
        if (row < 256) {
            int sp = row >> 7, r = row & 127;
            src = (const char*)g_wa + ((sp * 9 + tap) * 256 + oc0 + r) * 512 + icb;
            dst = sbase + sp * A_SEC + r * RSB;
        } else {
            int rowb = row - 256;
            int sp = rowb >> 8, p = rowb & 255;
            int yy = (yblk << 1) + (p >> 7) + ky;
            int xx = (p & 127) + kx;
            src = (const char*)g_tb + (sp * PADHW + yy * PADW + xx) * 512 + icb;
            dst = sbase + 2 * A_SEC + sp * B_SEC + p * RSB;
        }
        CP_ASYNC16(dst + c * 16, src + c * 16);
    }
    CP_COMMIT();
}

__global__ void __launch_bounds__(512, 1) conv_mma(const float* __restrict__ bias)
{
    extern __shared__ char dsm[];
    const uint32_t smem_base = smem_u32(dsm);
    const int tid = threadIdx.x;
    const int yblk = blockIdx.x;
    const int oc0 = blockIdx.y << 7;
    const int wid = tid >> 5, lane = tid & 31;
    const int wm = wid & 3, wn = wid >> 2;
    const int g = lane >> 2, t = lane & 3;

    float acc[2][8][4];
#pragma unroll
    for (int mt = 0; mt < 2; mt++)
#pragma unroll
        for (int nt = 0; nt < 8; nt++)
#pragma unroll
            for (int c = 0; c < 4; c++) acc[mt][nt][c] = 0.f;

    issue_stage(smem_base, 0, tid, yblk, oc0);
    CP_WAIT0();
    __syncthreads();

    for (int s = 0; s < NSTAGE; s++) {
        if (s + 1 < NSTAGE)
            issue_stage(smem_base + ((s + 1) & 1) * BUFB, s + 1, tid, yblk, oc0);

        const uint32_t* smw = (const uint32_t*)(dsm + (s & 1) * BUFB);
#pragma unroll
        for (int k16 = 0; k16 < 4; k16++) {
            const int ko = k16 * 8 + t;
            uint32_t af[2][2][4];
#pragma unroll
            for (int sp = 0; sp < 2; sp++)
#pragma unroll
                for (int mt = 0; mt < 2; mt++) {
                    int row = wm * 32 + mt * 16 + g;
                    int base = sp * (A_SEC / 4) + row * RSW + ko;
                    af[sp][mt][0] = smw[base];
                    af[sp][mt][1] = smw[base + 8 * RSW];
                    af[sp][mt][2] = smw[base + 4];
                    af[sp][mt][3] = smw[base + 8 * RSW + 4];
                }
#pragma unroll
            for (int sb = 0; sb < 2; sb++) {
                uint32_t bf_[8][2];
#pragma unroll
                for (int nt = 0; nt < 8; nt++) {
                    int n = wn * 64 + nt * 8 + g;
                    int base = 2 * (A_SEC / 4) + sb * (B_SEC / 4) + n * RSW + ko;
                    bf_[nt][0] = smw[base];
                    bf_[nt][1] = smw[base + 4];
                }
                const int nsa = (sb == 0) ? 2 : 1;
#pragma unroll
                for (int sa = 0; sa < 2; sa++) {
                    if (sa < nsa) {
#pragma unroll
                        for (int mt = 0; mt < 2; mt++)
#pragma unroll
                            for (int nt = 0; nt < 8; nt++)
                                MMA16816(acc[mt][nt], af[sa][mt], bf_[nt]);
                    }
                }
            }
        }

        if (s + 1 < NSTAGE) {
            CP_WAIT0();
            __syncthreads();
        }
    }

#pragma unroll
    for (int mt = 0; mt < 2; mt++) {
        int ocl = oc0 + wm * 32 + mt * 16 + g;
        float b0 = bias[ocl];
        float b1 = bias[ocl + 8];
#pragma unroll
        for (int nt = 0; nt < 8; nt++) {
            int col = wn * 64 + nt * 8 + 2 * t;
            float2 lo, hi;
            lo.x = fmaxf(acc[mt][nt][0] + b0, 0.f);
            lo.y = fmaxf(acc[mt][nt][1] + b0, 0.f);
            hi.x = fmaxf(acc[mt][nt][2] + b1, 0.f);
            hi.y = fmaxf(acc[mt][nt][3] + b1, 0.f);
            *(float2*)&g_rpnfeat[ocl * HW + yblk * 256 + col] = lo;
            *(float2*)&g_rpnfeat[(ocl + 8) * HW + yblk * 256 + col] = hi;
        }
    }
}

// =====================================================================
// heads (unchanged, passing)
// =====================================================================
#define HSM_FLOATS (11520 + 720)
#define HSM_BYTES  (HSM_FLOATS * 4)

__global__ __launch_bounds__(256)
void heads_sums(const float* __restrict__ cls_w, const float* __restrict__ cls_b,
                const float* __restrict__ bbox_w, const float* __restrict__ bbox_b)
{
    extern __shared__ float hsm[];
    float* ws   = hsm;
    float* red  = hsm;
    float* sums = hsm + 11520;

    const int tid = threadIdx.x;
    for (int i = tid; i < 9 * 256; i += 256)  ws[(i >> 8) * 256 + (i & 255)] = cls_w[i];
    for (int i = tid; i < 36 * 256; i += 256) ws[(9 + (i >> 8)) * 256 + (i & 255)] = bbox_w[i];
    __syncthreads();

    const int pl = tid & 15;
    const int q  = tid >> 4;
    const int p  = (blockIdx.x << 4) + pl;

    float acc[45];
#pragma unroll
    for (int j = 0; j < 45; j++) acc[j] = 0.f;

    const float* rf = g_rpnfeat + (q << 4) * HW + p;
    const float* wq = ws + (q << 4);
#pragma unroll
    for (int cc = 0; cc < 16; cc++) {
        float v = rf[cc * HW];
#pragma unroll
        for (int j = 0; j < 45; j++) acc[j] = fmaf(wq[j * 256 + cc], v, acc[j]);
    }
    __syncthreads();

    {
        float* r = red + (q * 16 + pl) * 45;
#pragma unroll
        for (int j = 0; j < 45; j++) r[j] = acc[j];
    }
    __syncthreads();

    for (int task = tid; task < 720; task += 256) {
        int pl2 = task / 45, j = task - pl2 * 45;
        float s = 0.f;
#pragma unroll
        for (int q2 = 0; q2 < 16; q2++)
            s += red[(q2 * 16 + pl2) * 45 + j];
        sums[pl2 * 45 + j] = s;
    }
    __syncthreads();

    if (tid < 144) {
        int pxl = tid / 9;
        int a   = tid - pxl * 9;
        const float* s = sums + pxl * 45;
        int pg = (blockIdx.x << 4) + pxl;
        int idx = pg * 9 + a;

        g_boxes[idx * 4 + 0] = s[9 + a * 4 + 0] + bbox_b[a * 4 + 0];
        g_boxes[idx * 4 + 1] = s[9 + a * 4 + 1] + bbox_b[a * 4 + 1];
        g_boxes[idx * 4 + 2] = s[9 + a * 4 + 2] + bbox_b[a * 4 + 2];
        g_boxes[idx * 4 + 3] = s[9 + a * 4 + 3] + bbox_b[a * 4 + 3];

        float cls = s[a] + cls_b[a];
        unsigned bb = __float_as_uint(cls);
        unsigned u = (bb & 0x80000000u) ? ~bb : (bb | 0x80000000u);
        g_keys[idx] = ((unsigned long long)u << 32) | (unsigned)(0xFFFFFFFFu - (unsigned)idx);
    }
}

// =====================================================================
// TAIL
// =====================================================================
__device__ void scan_phase(int* s, const int* h, int base, int phase)
{
    const int t = threadIdx.x;
    int c0 = h[4 * t], c1 = h[4 * t + 1], c2 = h[4 * t + 2], c3 = h[4 * t + 3];
    int v = c0 + c1 + c2 + c3;
    s[t] = v;
    __syncthreads();
    for (int off = 1; off < 1024; off <<= 1) {
        int add = (t + off < 1024) ? s[t + off] : 0;
        __syncthreads();
        v += add;
        s[t] = v;
        __syncthreads();
    }
    int suff = s[t];
    int above = (t < 1023) ? s[t + 1] : 0;
    if (base + above < TOPK && base + suff >= TOPK) {
        int cum = base + above;
        int c[4] = {c0, c1, c2, c3};
#pragma unroll
        for (int b = 3; b >= 0; b--) {
            if (cum + c[b] >= TOPK) {
                if (phase == 0) { g_B1 = 4 * t + b; g_cntgt = cum; }
                else            { g_T = ((unsigned)g_B1 << 12) | (unsigned)(4 * t + b); }
                break;
            }
            cum += c[b];
        }
    }
    __syncthreads();
}

__global__ __launch_bounds__(1024)
void tail(float* __restrict__ out)
{
    extern __shared__ char dsm[];
    const int tid = threadIdx.x;
    const int b = blockIdx.x;

    // ---- A: hist1 ----
    {
        int* h = (int*)dsm;
        for (int i = tid; i < 4096; i += 1024) h[i] = 0;
        __syncthreads();
        for (int i = b * 1024 + tid; i < NANCH; i += GRIDT * 1024)
            atomicAdd(&h[(unsigned)(g_keys[i] >> 52)], 1);
        __syncthreads();
        for (int i = tid; i < 4096; i += 1024) {
            int v = h[i];
            if (v) atomicAdd(&g_hist1[i], v);
        }
    }
    gsync(0);
    if (b == 0) scan_phase((int*)dsm, g_hist1, 0, 0);
    gsync(1);
    {
        const unsigned b1 = (unsigned)(*(volatile int*)&g_B1);
        int* h = (int*)dsm;
        for (int i = tid; i < 4096; i += 1024) h[i] = 0;
        __syncthreads();
        for (int i = b * 1024 + tid; i < NANCH; i += GRIDT * 1024) {
            unsigned long long key = g_keys[i];
            if ((unsigned)(key >> 52) == b1)
                atomicAdd(&h[(unsigned)((key >> 40) & 0xFFFull)], 1);
        }
        __syncthreads();
        for (int i = tid; i < 4096; i += 1024) {
            int v = h[i];
            if (v) atomicAdd(&g_hist2[i], v);
        }
    }
    gsync(2);
    if (b == 0) scan_phase((int*)dsm, g_hist2, *(volatile int*)&g_cntgt, 1);
    gsync(3);

    // ---- E: compact + parallel decode ----
    {
        const float AR[3]  = {0.5f, 1.0f, 2.0f};
        const float SCL[3] = {128.f, 256.f, 512.f};
        const unsigned T = *(volatile unsigned*)&g_T;
        for (int i = b * 1024 + tid; i < NANCH; i += GRIDT * 1024) {
            unsigned long long key = g_keys[i];
            if ((unsigned)(key >> 40) >= T) {
                int p = atomicAdd(&g_selcnt, 1);
                if (p < NSEL) g_sel[p] = key;

                float4 d = *(const float4*)&g_boxes[i * 4];
                int pg = i / 9;
                int a = i - pg * 9;
                float sx = (float)(pg & 127) * STRIDE;
                float sy = (float)(pg >> 7) * STRIDE;
                int ia = a / 3, is_ = a - ia * 3;
                float hr  = sqrtf(AR[ia]);
                float wr  = __frcp_rn(hr);
                float hsv = __fmul_rn(hr, SCL[is_]);
                float wsv = __fmul_rn(wr, SCL[is_]);
                float bx1 = rintf(__fmul_rn(-wsv, 0.5f));
                float by1 = rintf(__fmul_rn(-hsv, 0.5f));
                float bx2 = rintf(__fmul_rn(wsv, 0.5f));
                float by2 = rintf(__fmul_rn(hsv, 0.5f));
                float ax1 = __fadd_rn(sx, bx1), ay1 = __fadd_rn(sy, by1);
                float ax2 = __fadd_rn(sx, bx2), ay2 = __fadd_rn(sy, by2);
                float aw = __fsub_rn(ax2, ax1), ah = __fsub_rn(ay2, ay1);
                float cx = __fadd_rn(ax1, __fmul_rn(0.5f, aw));
                float cy = __fadd_rn(ay1, __fmul_rn(0.5f, ah));

                float dw = fminf(d.z, DWCLIP);
                float dh = fminf(d.w, DWCLIP);
                float px = __fadd_rn(__fmul_rn(d.x, aw), cx);
                float py = __fadd_rn(__fmul_rn(d.y, ah), cy);
                float pw = __fmul_rn((float)exp((double)dw), aw);
                float ph = __fmul_rn((float)exp((double)dh), ah);

                float x1 = __fsub_rn(px, __fmul_rn(0.5f, pw));
                float y1 = __fsub_rn(py, __fmul_rn(0.5f, ph));
                float x2 = __fadd_rn(px, __fmul_rn(0.5f, pw));
                float y2 = __fadd_rn(py, __fmul_rn(0.5f, ph));

                x1 = fminf(fmaxf(x1, 0.f), IMSZ);
                y1 = fminf(fmaxf(y1, 0.f), IMSZ);
                x2 = fminf(fmaxf(x2, 0.f), IMSZ);
                y2 = fminf(fmaxf(y2, 0.f), IMSZ);
                float wv = __fsub_rn(x2, x1);
                float hv = __fsub_rn(y2, y1);
                float ar = __fmul_rn(wv, hv);
                if (!(wv >= MINSZ && hv >= MINSZ)) ar = -1.f;

                g_dx1[i] = x1; g_dy1[i] = y1; g_dx2[i] = x2; g_dy2[i] = y2; g_dar[i] = ar;
            }
        }
    }
    gsync(4);

    // ---- F1: parallel sort on blocks 0-3 ----
    if (b < 4) {
        unsigned long long* sk = (unsigned long long*)dsm;
        const int cbase = b << 11;

        sk[tid]        = g_sel[cbase + tid];
        sk[tid + 1024] = g_sel[cbase + tid + 1024];
        __syncthreads();
        for (int k = 2; k <= 2048; k <<= 1) {
            for (int j = k >> 1; j > 0; j >>= 1) {
                int t = tid;
                int i = (t << 1) - (t & (j - 1));
                bool desc = (((cbase + i) & k) == 0);
                unsigned long long x = sk[i], y = sk[i + j];
                if ((x < y) == desc) { sk[i] = y; sk[i + j] = x; }
                __syncthreads();
            }
        }
        g_sel[cbase + tid]        = sk[tid];
        g_sel[cbase + tid + 1024] = sk[tid + 1024];
        sync4(10);

        {
            int t4 = (b << 10) + tid;
            int i = (t4 << 1) - (t4 & 2047);
            bool desc = ((i & 4096) == 0);
            unsigned long long x = g_sel[i], y = g_sel[i + 2048];
            if ((x < y) == desc) { g_sel[i] = y; g_sel[i + 2048] = x; }
        }
        sync4(11);

        sk[tid]        = g_sel[cbase + tid];
        sk[tid + 1024] = g_sel[cbase + tid + 1024];
        __syncthreads();
        for (int j = 1024; j > 0; j >>= 1) {
            int t = tid;
            int i = (t << 1) - (t & (j - 1));
            bool desc = (((cbase + i) & 4096) == 0);
            unsigned long long x = sk[i], y = sk[i + j];
            if ((x < y) == desc) { sk[i] = y; sk[i + j] = x; }
            __syncthreads();
        }
        g_sel[cbase + tid]        = sk[tid];
        g_sel[cbase + tid + 1024] = sk[tid + 1024];
        sync4(12);

        {
            int t4 = (b << 10) + tid;
            unsigned long long x = g_sel[t4], y = g_sel[t4 + 4096];
            if (x < y) { g_sel[t4] = y; g_sel[t4 + 4096] = x; }
        }
        sync4(13);

        {
            int t4 = (b << 10) + tid;
            int i = (t4 << 1) - (t4 & 2047);
            unsigned long long x = g_sel[i], y = g_sel[i + 2048];
            if (x < y) { g_sel[i] = y; g_sel[i + 2048] = x; }
        }
        sync4(14);

        sk[tid]        = g_sel[cbase + tid];
        sk[tid + 1024] = g_sel[cbase + tid + 1024];
        __syncthreads();
        for (int j = 1024; j > 0; j >>= 1) {
            int t = tid;
            int i = (t << 1) - (t & (j - 1));
            unsigned long long x = sk[i], y = sk[i + j];
            if (x < y) { sk[i] = y; sk[i + j] = x; }
            __syncthreads();
        }
        g_sel[cbase + tid]        = sk[tid];
        g_sel[cbase + tid + 1024] = sk[tid + 1024];
    }
    gsync(5);

    // ---- G: ordered box arrays ----
    for (int j = b * 1024 + tid; j < TOPK; j += GRIDT * 1024) {
        unsigned long long key = g_sel[j];
        unsigned idx = 0xFFFFFFFFu - (unsigned)(key & 0xFFFFFFFFull);
        float4 bx = make_float4(0.f, 0.f, 0.f, 0.f);
        float ar = -1.f;
        if (idx < (unsigned)NANCH) {
            bx = make_float4(g_dx1[idx], g_dy1[idx], g_dx2[idx], g_dy2[idx]);
            ar = g_dar[idx];
        }
        g_obx[j] = bx;
        g_oar[j] = ar;
    }
    gsync(6);

    // ---- H: load boxes to smem; compute matrix chunk 0 (all blocks) ----
    float4* sb4 = (float4*)dsm;
    float* sar2 = (float*)(dsm + 96000);
    for (int j = tid; j < TOPK; j += 1024) {
        sb4[j] = g_obx[j];
        sar2[j] = g_oar[j];
    }
    __syncthreads();

    mat_rows(sb4, sar2, 0, CHUNK, b * 1024 + tid, GRIDT * 1024);
    gsync(7);

    // ---- worker pool (blocks 1..147): lazy chunks on demand ----
    if (b != 0) {
        __shared__ int cmd;
        int next = 1;
        for (;;) {
            if (tid == 0) {
                int w;
                for (;;) {
                    w = atomicAdd(&g_work, 0);
                    if (w == -1 || w >= next) break;
                    __nanosleep(128);
                }
                cmd = w;
            }
            __syncthreads();
            int w = cmd;
            if (w == -1) return;
            int r0 = next * CHUNK;
            int r1 = min(r0 + CHUNK, TOPK);
            mat_rows(sb4, sar2, r0, r1, (b - 1) * 1024 + tid, (GRIDT - 1) * 1024);
            __threadfence();
            __syncthreads();
            if (tid == 0) atomicAdd(&g_bars[20 + next], 1);
            next++;
            if (next >= NCHUNK) return;
        }
    }

    // ---- I (block 0): greedy over bitmap with lazy chunk requests ----
    unsigned* removed = (unsigned*)(dsm + 120064);
    __shared__ int keepList[POSTK];
    {
        const int warpid = tid >> 5, lane = tid & 31;
#pragma unroll
        for (int q = 0; q < 6; q++) {
            int wd = q * 32 + warpid;
            if (wd < NBITW) {
                int j = (wd << 5) + lane;
                bool bad = (j >= TOPK) || (sar2[j] < 0.f);
                unsigned m = __ballot_sync(0xFFFFFFFFu, bad);
                if (lane == 0) removed[wd] = m;
            }
        }
    }
    __syncthreads();

    int count = 0;
    int i = 0;
    int limit = CHUNK;
    for (;;) {
        while (i < TOPK) {
            unsigned wv = (~removed[i >> 5]) & (0xFFFFFFFFu << (i & 31));
            if (wv) { i = (i & ~31) + (__ffs(wv) - 1); break; }
            i = (i & ~31) + 32;
        }
        if (i >= TOPK) break;
        while (i >= limit) {                       // need more matrix rows
            int k = limit / CHUNK;
            if (tid == 0) {
                atomicExch(&g_work, k);
                while (atomicAdd(&g_bars[20 + k], 0) < GRIDT - 1) { __nanosleep(128); }
            }
            __syncthreads();
            __threadfence();
            limit += CHUNK;
        }
        if (tid == 0) keepList[count] = i;
        count++;
        if (count >= POSTK) break;
        if (tid < NBITW) removed[tid] |= g_mat[i * NBITW + tid];
        i++;
        __syncthreads();
    }
    __syncthreads();
    if (tid == 0) atomicExch(&g_work, -1);         // release workers

    for (int t = tid; t < POSTK; t += 1024) {
        if (t < count) {
            int ii = keepList[t];
            float4 bb4 = sb4[ii];
            unsigned long long key = g_sel[ii];
            unsigned u = (unsigned)(key >> 32);
            unsigned bb = (u & 0x80000000u) ? (u & 0x7FFFFFFFu) : ~u;
            float cls = __uint_as_float(bb);
            float sc = (float)(1.0 / (1.0 + exp(-(double)cls)));
            out[t * 5 + 0] = bb4.x;
            out[t * 5 + 1] = bb4.y;
            out[t * 5 + 2] = bb4.z;
            out[t * 5 + 3] = bb4.w;
            out[t * 5 + 4] = sc;
        } else {
            out[t * 5 + 0] = 0.f; out[t * 5 + 1] = 0.f; out[t * 5 + 2] = 0.f;
            out[t * 5 + 3] = 0.f; out[t * 5 + 4] = 0.f;
        }
    }
}

// ---------------- launch ----------------
extern "C" void kernel_launch(void* const* d_in, const int* in_sizes, int n_in,
                              void* d_out, int out_size)
{
    (void)in_sizes; (void)n_in; (void)out_size;
    const float* feat   = (const float*)d_in[1];
    const float* conv_w = (const float*)d_in[2];
    const float* conv_b = (const float*)d_in[3];
    const float* cls_w  = (const float*)d_in[4];
    const float* cls_b  = (const float*)d_in[5];
    const float* bbox_w = (const float*)d_in[6];
    const float* bbox_b = (const float*)d_in[7];
    float* out = (float*)d_out;

    prep_all<<<4371, 1024>>>(feat, conv_w);

    cudaFuncSetAttribute(conv_mma, cudaFuncAttributeMaxDynamicSharedMemorySize, DYNSM);
    conv_mma<<<dim3(64, 2), 512, DYNSM>>>(conv_b);

    cudaFuncSetAttribute(heads_sums, cudaFuncAttributeMaxDynamicSharedMemorySize, HSM_BYTES);
    heads_sums<<<1024, 256, HSM_BYTES>>>(cls_w, cls_b, bbox_w, bbox_b);

    cudaFuncSetAttribute(tail, cudaFuncAttributeMaxDynamicSharedMemorySize, TAILSM);
    tail<<<GRIDT, 1024, TAILSM>>>(out);
}

// round 15
// speedup vs baseline: 5.3900x; 1.0283x over previous
#include <cuda_runtime.h>
#include <cuda_fp16.h>
#include <cstdint>
#include <math.h>

// ---------------- problem constants ----------------
#define HW      16384
#define CH      256
#define NANCH   147456
#define TOPK    6000
#define POSTK   300
#define STRIDE  8.0f
#define IMSZ    1024.0f
#define DWCLIP  4.135166556742356f
#define NMSTHR  0.7f
#define MINSZ   16.0f
#define MTHR    0x1.666667p-1    // midpoint(0.7f, nextafterf(0.7f)), exact in double

#define PADW    132
#define PADH    130
#define PADHW   (PADW*PADH)

#define NSEL    8192
#define NBITW   188
#define CHUNK   512
#define NCHUNK  12

// conv tiling
#define NSTAGE  36
#define RSB     144
#define RSW     36
#define A_SEC   18432
#define B_SEC   36864
#define BUFB    (2*A_SEC + 2*B_SEC)
#define DYNSM   (2*BUFB)

// tail
#define GRIDT   148
#define TAILSM  121088

// ---------------- scratch ----------------
__device__ float g_rpnfeat[CH * HW];
__device__ __align__(256) __half g_tb[2 * PADHW * 256];
__device__ __align__(256) __half g_wa[2 * 9 * 256 * 256];
__device__ float g_boxes[NANCH * 4];
__device__ unsigned long long g_keys[NANCH];
__device__ unsigned long long g_sel[NSEL];
__device__ float g_dx1[NANCH], g_dy1[NANCH], g_dx2[NANCH], g_dy2[NANCH], g_dar[NANCH];
__device__ unsigned g_mat[TOPK * NBITW];
__device__ int g_hist1[4096];
__device__ int g_hist2[4096];
__device__ int g_B1;
__device__ int g_cntgt;
__device__ unsigned g_T;
__device__ int g_selcnt;
__device__ int g_work;
__device__ int g_bars[64];

// ---------------- helpers ----------------
__device__ __forceinline__ uint32_t smem_u32(const void* p) {
    uint32_t a;
    asm("{ .reg .u64 t; cvta.to.shared.u64 t, %1; cvt.u32.u64 %0, t; }" : "=r"(a) : "l"(p));
    return a;
}
#define CP_ASYNC16(dst, src) \
    asm volatile("cp.async.cg.shared.global [%0], [%1], 16;" :: "r"(dst), "l"(src))
#define CP_COMMIT()  asm volatile("cp.async.commit_group;" ::: "memory")
#define CP_WAIT0()   asm volatile("cp.async.wait_group 0;" ::: "memory")

#define MMA16816(d, a, b) \
    asm volatile("mma.sync.aligned.m16n8k16.row.col.f32.f16.f16.f32 " \
        "{%0,%1,%2,%3}, {%4,%5,%6,%7}, {%8,%9}, {%0,%1,%2,%3};" \
        : "+f"((d)[0]), "+f"((d)[1]), "+f"((d)[2]), "+f"((d)[3]) \
        : "r"((a)[0]), "r"((a)[1]), "r"((a)[2]), "r"((a)[3]), "r"((b)[0]), "r"((b)[1]))

#define LDSM4(r, addr) \
    asm volatile("ldmatrix.sync.aligned.m8n8.x4.shared.b16 {%0,%1,%2,%3}, [%4];" \
        : "=r"((r)[0]), "=r"((r)[1]), "=r"((r)[2]), "=r"((r)[3]) : "r"(addr))

__device__ __forceinline__ void gsync(int k) {
    __threadfence();
    __syncthreads();
    if (threadIdx.x == 0) {
        atomicAdd(&g_bars[k], 1);
        while (*(volatile int*)&g_bars[k] < GRIDT) { __nanosleep(64); }
    }
    __syncthreads();
}
__device__ __forceinline__ void sync4(int k) {
    __threadfence();
    __syncthreads();
    if (threadIdx.x == 0) {
        atomicAdd(&g_bars[k], 1);
        while (*(volatile int*)&g_bars[k] < 4) { __nanosleep(32); }
    }
    __syncthreads();
}

// exact-decision IoU suppression test (bit-identical to RN(inter/denom) > 0.7f)
__device__ __forceinline__ bool iou_sup(float4 bi, float ai, float4 bj, float aj) {
    float xx1 = fmaxf(bi.x, bj.x);
    float yy1 = fmaxf(bi.y, bj.y);
    float xx2 = fminf(bi.z, bj.z);
    float yy2 = fminf(bi.w, bj.w);
    float iw = fmaxf(__fsub_rn(xx2, xx1), 0.f);
    float ih = fmaxf(__fsub_rn(yy2, yy1), 0.f);
    float inter = __fmul_rn(iw, ih);
    float denom = __fsub_rn(__fadd_rn(ai, aj), inter);
    float lo = __fmul_rn(0.699f, denom);
    float hi = __fmul_rn(0.701f, denom);
    if (inter <= lo) return false;
    if (inter >= hi) return true;
    return (double)inter >= MTHR * (double)denom;
}

__device__ void mat_rows(const float4* sb4, const float* sar2, int r0, int r1,
                         int gidx, int gstride)
{
    for (int task = r0 * NBITW + gidx; task < r1 * NBITW; task += gstride) {
        int r = task / NBITW;
        int w = task - r * NBITW;
        float4 bi = sb4[r];
        float ai = sar2[r];
        unsigned bits = 0u;
        int j0 = w << 5;
        int jend = min(j0 + 32, TOPK);
        for (int j = (j0 > r + 1 ? j0 : r + 1); j < jend; j++) {
            if (iou_sup(bi, ai, sb4[j], sar2[j])) bits |= 1u << (j - j0);
        }
        g_mat[task] = bits;
    }
}

// =====================================================================
// fused prep (unchanged, passing)
// =====================================================================
__global__ __launch_bounds__(1024)
void prep_all(const float* __restrict__ feat, const float* __restrict__ w)
{
    __shared__ float sm[32][33];
    const int b = blockIdx.x;
    const int tid = threadIdx.x;

    if (b < 4096) {
        const int px0 = (b & 511) << 5;
        const int ic0 = (b >> 9) << 5;
        const int tx = tid & 31, ty = tid >> 5;
        sm[ty][tx] = feat[(ic0 + ty) * HW + px0 + tx];
        __syncthreads();
        float v = sm[tx][ty];
        __half h0 = __float2half_rn(v);
        __half h1 = __float2half_rn(v - __half2float(h0));
        const int p = px0 + ty;
        const int padpos = ((p >> 7) + 1) * PADW + (p & 127) + 1;
        const int waddr = padpos * 256 + ic0 + tx;
        g_tb[waddr] = h0;
        g_tb[PADHW * 256 + waddr] = h1;
    } else if (b < 4160) {
        int idx = (b - 4096) * 1024 + tid;
        int oc = idx >> 8, ic = idx & 255;
#pragma unroll
        for (int tap = 0; tap < 9; tap++) {
            float x = w[oc * 2304 + ic * 9 + tap];
            __half h0 = __float2half_rn(x);
            __half h1 = __float2half_rn(x - __half2float(h0));
            int base = (tap * 256 + oc) * 256 + ic;
            g_wa[base] = h0;
            g_wa[9 * 65536 + base] = h1;
        }
    } else if (b < 4354) {
        int gid = (b - 4160) * 1024 + tid;
        if (gid < 776 * 256) {
            int hid = gid >> 8, ic = gid & 255;
            int yp, xp;
            if (hid < 132)      { yp = 0;   xp = hid; }
            else if (hid < 264) { yp = 129; xp = hid - 132; }
            else {
                int r = hid - 264;
                yp = 1 + (r >> 2);
                int c = r & 3;
                xp = (c == 0) ? 0 : 128 + c;
            }
            int base = (yp * PADW + xp) * 256 + ic;
            g_tb[base] = __float2half_rn(0.f);
            g_tb[PADHW * 256 + base] = __float2half_rn(0.f);
        }
    } else {
        int gid = (b - 4354) * 1024 + tid;
        if (gid < 4096) g_hist1[gid] = 0;
        else if (gid < 8192) g_hist2[gid - 4096] = 0;
        else if (gid < 16384) g_sel[gid - 8192] = 0ull;
        else if (gid < 16448) g_bars[gid - 16384] = 0;
        else if (gid == 16448) g_selcnt = 0;
        else if (gid == 16449) g_B1 = 0;
        else if (gid == 16450) g_cntgt = 0;
        else if (gid == 16451) g_T = 0u;
        else if (gid == 16452) g_work = 0;
    }
}

// =====================================================================
// conv: same pipeline; fragment loads via ldmatrix.x4 (values identical)
// =====================================================================
__device__ __forceinline__ void issue_stage(uint32_t sbase, int s, int tid, int yblk, int oc0)
{
    const int tap = s >> 2;
    const int icb = (s & 3) << 7;
    const int ky = tap / 3, kx = tap - ky * 3;
#pragma unroll
    for (int i = 0; i < 12; i++) {
        int cid = tid + (i << 9);
        int row = cid >> 3, c = cid & 7;
        const char* src;
        uint32_t dst;
        if (row < 256) {
            int sp = row >> 7, r = row & 127;
            src = (const char*)g_wa + ((sp * 9 + tap) * 256 + oc0 + r) * 512 + icb;
            dst = sbase + sp * A_SEC + r * RSB;
        } else {
            int rowb = row - 256;
            int sp = rowb >> 8, p = rowb & 255;
            int yy = (yblk << 1) + (p >> 7) + ky;
            int xx = (p & 127) + kx;
            src = (const char*)g_tb + (sp * PADHW + yy * PADW + xx) * 512 + icb;
            dst = sbase + 2 * A_SEC + sp * B_SEC + p * RSB;
        }
        CP_ASYNC16(dst + c * 16, src + c * 16);
    }
    CP_COMMIT();
}

__global__ void __launch_bounds__(512, 1) conv_mma(const float* __restrict__ bias)
{
    extern __shared__ char dsm[];
    const uint32_t smem_base = smem_u32(dsm);
    const int tid = threadIdx.x;
    const int yblk = blockIdx.x;
    const int oc0 = blockIdx.y << 7;
    const int wid = tid >> 5, lane = tid & 31;
    const int wm = wid & 3, wn = wid >> 2;
    const int g = lane >> 2, t = lane & 3;

    // ldmatrix lane offsets
    const int lm = lane >> 3, rin = lane & 7;
    const uint32_t laneA = (uint32_t)(rin * RSB + (lm & 1) * (8 * RSB) + (lm >> 1) * 16);
    const uint32_t laneB = (uint32_t)(rin * RSB + ((lm >> 1) & 1) * (8 * RSB) + (lm & 1) * 16);
    const uint32_t baseA = (uint32_t)((wm * 32) * RSB) + laneA;
    const uint32_t baseB = (uint32_t)(2 * A_SEC + (wn * 64) * RSB) + laneB;

    float acc[2][8][4];
#pragma unroll
    for (int mt = 0; mt < 2; mt++)
#pragma unroll
        for (int nt = 0; nt < 8; nt++)
#pragma unroll
            for (int c = 0; c < 4; c++) acc[mt][nt][c] = 0.f;

    issue_stage(smem_base, 0, tid, yblk, oc0);
    CP_WAIT0();
    __syncthreads();

    for (int s = 0; s < NSTAGE; s++) {
        if (s + 1 < NSTAGE)
            issue_stage(smem_base + ((s + 1) & 1) * BUFB, s + 1, tid, yblk, oc0);

        const uint32_t dynb = smem_base + (uint32_t)((s & 1) * BUFB);
#pragma unroll
        for (int k16 = 0; k16 < 4; k16++) {
            const uint32_t koff = (uint32_t)(k16 * 32);
            uint32_t af[2][2][4];
#pragma unroll
            for (int sp = 0; sp < 2; sp++)
#pragma unroll
                for (int mt = 0; mt < 2; mt++) {
                    uint32_t addr = dynb + (uint32_t)(sp * A_SEC) + baseA
                                  + (uint32_t)(mt * 16 * RSB) + koff;
                    LDSM4(af[sp][mt], addr);
                }
#pragma unroll
            for (int sb = 0; sb < 2; sb++) {
                uint32_t bf_[8][2];
#pragma unroll
                for (int ntp = 0; ntp < 4; ntp++) {
                    uint32_t r4[4];
                    uint32_t addr = dynb + baseB + (uint32_t)(sb * B_SEC)
                                  + (uint32_t)(ntp * 16 * RSB) + koff;
                    LDSM4(r4, addr);
                    bf_[2 * ntp][0] = r4[0];
                    bf_[2 * ntp][1] = r4[1];
                    bf_[2 * ntp + 1][0] = r4[2];
                    bf_[2 * ntp + 1][1] = r4[3];
                }
                const int nsa = (sb == 0) ? 2 : 1;
#pragma unroll
                for (int sa = 0; sa < 2; sa++) {
                    if (sa < nsa) {
#pragma unroll
                        for (int mt = 0; mt < 2; mt++)
#pragma unroll
                            for (int nt = 0; nt < 8; nt++)
                                MMA16816(acc[mt][nt], af[sa][mt], bf_[nt]);
                    }
                }
            }
        }

        if (s + 1 < NSTAGE) {
            CP_WAIT0();
            __syncthreads();
        }
    }

#pragma unroll
    for (int mt = 0; mt < 2; mt++) {
        int ocl = oc0 + wm * 32 + mt * 16 + g;
        float b0 = bias[ocl];
        float b1 = bias[ocl + 8];
#pragma unroll
        for (int nt = 0; nt < 8; nt++) {
            int col = wn * 64 + nt * 8 + 2 * t;
            float2 lo, hi;
            lo.x = fmaxf(acc[mt][nt][0] + b0, 0.f);
            lo.y = fmaxf(acc[mt][nt][1] + b0, 0.f);
            hi.x = fmaxf(acc[mt][nt][2] + b1, 0.f);
            hi.y = fmaxf(acc[mt][nt][3] + b1, 0.f);
            *(float2*)&g_rpnfeat[ocl * HW + yblk * 256 + col] = lo;
            *(float2*)&g_rpnfeat[(ocl + 8) * HW + yblk * 256 + col] = hi;
        }
    }
}

// =====================================================================
// heads (unchanged, passing)
// =====================================================================
#define HSM_FLOATS (11520 + 720)
#define HSM_BYTES  (HSM_FLOATS * 4)

__global__ __launch_bounds__(256)
void heads_sums(const float* __restrict__ cls_w, const float* __restrict__ cls_b,
                const float* __restrict__ bbox_w, const float* __restrict__ bbox_b)
{
    extern __shared__ float hsm[];
    float* ws   = hsm;
    float* red  = hsm;
    float* sums = hsm + 11520;

    const int tid = threadIdx.x;
    for (int i = tid; i < 9 * 256; i += 256)  ws[(i >> 8) * 256 + (i & 255)] = cls_w[i];
    for (int i = tid; i < 36 * 256; i += 256) ws[(9 + (i >> 8)) * 256 + (i & 255)] = bbox_w[i];
    __syncthreads();

    const int pl = tid & 15;
    const int q  = tid >> 4;
    const int p  = (blockIdx.x << 4) + pl;

    float acc[45];
#pragma unroll
    for (int j = 0; j < 45; j++) acc[j] = 0.f;

    const float* rf = g_rpnfeat + (q << 4) * HW + p;
    const float* wq = ws + (q << 4);
#pragma unroll
    for (int cc = 0; cc < 16; cc++) {
        float v = rf[cc * HW];
#pragma unroll
        for (int j = 0; j < 45; j++) acc[j] = fmaf(wq[j * 256 + cc], v, acc[j]);
    }
    __syncthreads();

    {
        float* r = red + (q * 16 + pl) * 45;
#pragma unroll
        for (int j = 0; j < 45; j++) r[j] = acc[j];
    }
    __syncthreads();

    for (int task = tid; task < 720; task += 256) {
        int pl2 = task / 45, j = task - pl2 * 45;
        float s = 0.f;
#pragma unroll
        for (int q2 = 0; q2 < 16; q2++)
            s += red[(q2 * 16 + pl2) * 45 + j];
        sums[pl2 * 45 + j] = s;
    }
    __syncthreads();

    if (tid < 144) {
        int pxl = tid / 9;
        int a   = tid - pxl * 9;
        const float* s = sums + pxl * 45;
        int pg = (blockIdx.x << 4) + pxl;
        int idx = pg * 9 + a;

        g_boxes[idx * 4 + 0] = s[9 + a * 4 + 0] + bbox_b[a * 4 + 0];
        g_boxes[idx * 4 + 1] = s[9 + a * 4 + 1] + bbox_b[a * 4 + 1];
        g_boxes[idx * 4 + 2] = s[9 + a * 4 + 2] + bbox_b[a * 4 + 2];
        g_boxes[idx * 4 + 3] = s[9 + a * 4 + 3] + bbox_b[a * 4 + 3];

        float cls = s[a] + cls_b[a];
        unsigned bb = __float_as_uint(cls);
        unsigned u = (bb & 0x80000000u) ? ~bb : (bb | 0x80000000u);
        g_keys[idx] = ((unsigned long long)u << 32) | (unsigned)(0xFFFFFFFFu - (unsigned)idx);
    }
}

// =====================================================================
// TAIL
// =====================================================================
__device__ void scan_phase(int* s, const int* h, int base, int phase)
{
    const int t = threadIdx.x;
    int c0 = h[4 * t], c1 = h[4 * t + 1], c2 = h[4 * t + 2], c3 = h[4 * t + 3];
    int v = c0 + c1 + c2 + c3;
    s[t] = v;
    __syncthreads();
    for (int off = 1; off < 1024; off <<= 1) {
        int add = (t + off < 1024) ? s[t + off] : 0;
        __syncthreads();
        v += add;
        s[t] = v;
        __syncthreads();
    }
    int suff = s[t];
    int above = (t < 1023) ? s[t + 1] : 0;
    if (base + above < TOPK && base + suff >= TOPK) {
        int cum = base + above;
        int c[4] = {c0, c1, c2, c3};
#pragma unroll
        for (int b = 3; b >= 0; b--) {
            if (cum + c[b] >= TOPK) {
                if (phase == 0) { g_B1 = 4 * t + b; g_cntgt = cum; }
                else            { g_T = ((unsigned)g_B1 << 12) | (unsigned)(4 * t + b); }
                break;
            }
            cum += c[b];
        }
    }
    __syncthreads();
}

__global__ __launch_bounds__(1024)
void tail(float* __restrict__ out)
{
    extern __shared__ char dsm[];
    const int tid = threadIdx.x;
    const int b = blockIdx.x;

    // ---- A: hist1 ----
    {
        int* h = (int*)dsm;
        for (int i = tid; i < 4096; i += 1024) h[i] = 0;
        __syncthreads();
        for (int i = b * 1024 + tid; i < NANCH; i += GRIDT * 1024)
            atomicAdd(&h[(unsigned)(g_keys[i] >> 52)], 1);
        __syncthreads();
        for (int i = tid; i < 4096; i += 1024) {
            int v = h[i];
            if (v) atomicAdd(&g_hist1[i], v);
        }
    }
    gsync(0);
    if (b == 0) scan_phase((int*)dsm, g_hist1, 0, 0);
    gsync(1);
    {
        const unsigned b1 = (unsigned)(*(volatile int*)&g_B1);
        int* h = (int*)dsm;
        for (int i = tid; i < 4096; i += 1024) h[i] = 0;
        __syncthreads();
        for (int i = b * 1024 + tid; i < NANCH; i += GRIDT * 1024) {
            unsigned long long key = g_keys[i];
            if ((unsigned)(key >> 52) == b1)
                atomicAdd(&h[(unsigned)((key >> 40) & 0xFFFull)], 1);
        }
        __syncthreads();
        for (int i = tid; i < 4096; i += 1024) {
            int v = h[i];
            if (v) atomicAdd(&g_hist2[i], v);
        }
    }
    gsync(2);
    if (b == 0) scan_phase((int*)dsm, g_hist2, *(volatile int*)&g_cntgt, 1);
    gsync(3);

    // ---- E: compact + parallel decode ----
    {
        const float AR[3]  = {0.5f, 1.0f, 2.0f};
        const float SCL[3] = {128.f, 256.f, 512.f};
        const unsigned T = *(volatile unsigned*)&g_T;
        for (int i = b * 1024 + tid; i < NANCH; i += GRIDT * 1024) {
            unsigned long long key = g_keys[i];
            if ((unsigned)(key >> 40) >= T) {
                int p = atomicAdd(&g_selcnt, 1);
                if (p < NSEL) g_sel[p] = key;

                float4 d = *(const float4*)&g_boxes[i * 4];
                int pg = i / 9;
                int a = i - pg * 9;
                float sx = (float)(pg & 127) * STRIDE;
                float sy = (float)(pg >> 7) * STRIDE;
                int ia = a / 3, is_ = a - ia * 3;
                float hr  = sqrtf(AR[ia]);
                float wr  = __frcp_rn(hr);
                float hsv = __fmul_rn(hr, SCL[is_]);
                float wsv = __fmul_rn(wr, SCL[is_]);
                float bx1 = rintf(__fmul_rn(-wsv, 0.5f));
                float by1 = rintf(__fmul_rn(-hsv, 0.5f));
                float bx2 = rintf(__fmul_rn(wsv, 0.5f));
                float by2 = rintf(__fmul_rn(hsv, 0.5f));
                float ax1 = __fadd_rn(sx, bx1), ay1 = __fadd_rn(sy, by1);
                float ax2 = __fadd_rn(sx, bx2), ay2 = __fadd_rn(sy, by2);
                float aw = __fsub_rn(ax2, ax1), ah = __fsub_rn(ay2, ay1);
                float cx = __fadd_rn(ax1, __fmul_rn(0.5f, aw));
                float cy = __fadd_rn(ay1, __fmul_rn(0.5f, ah));

                float dw = fminf(d.z, DWCLIP);
                float dh = fminf(d.w, DWCLIP);
                float px = __fadd_rn(__fmul_rn(d.x, aw), cx);
                float py = __fadd_rn(__fmul_rn(d.y, ah), cy);
                float pw = __fmul_rn((float)exp((double)dw), aw);
                float ph = __fmul_rn((float)exp((double)dh), ah);

                float x1 = __fsub_rn(px, __fmul_rn(0.5f, pw));
                float y1 = __fsub_rn(py, __fmul_rn(0.5f, ph));
                float x2 = __fadd_rn(px, __fmul_rn(0.5f, pw));
                float y2 = __fadd_rn(py, __fmul_rn(0.5f, ph));

                x1 = fminf(fmaxf(x1, 0.f), IMSZ);
                y1 = fminf(fmaxf(y1, 0.f), IMSZ);
                x2 = fminf(fmaxf(x2, 0.f), IMSZ);
                y2 = fminf(fmaxf(y2, 0.f), IMSZ);
                float wv = __fsub_rn(x2, x1);
                float hv = __fsub_rn(y2, y1);
                float ar = __fmul_rn(wv, hv);
                if (!(wv >= MINSZ && hv >= MINSZ)) ar = -1.f;

                g_dx1[i] = x1; g_dy1[i] = y1; g_dx2[i] = x2; g_dy2[i] = y2; g_dar[i] = ar;
            }
        }
    }
    gsync(4);

    // ---- F1: parallel sort on blocks 0-3 ----
    if (b < 4) {
        unsigned long long* sk = (unsigned long long*)dsm;
        const int cbase = b << 11;

        sk[tid]        = g_sel[cbase + tid];
        sk[tid + 1024] = g_sel[cbase + tid + 1024];
        __syncthreads();
        for (int k = 2; k <= 2048; k <<= 1) {
            for (int j = k >> 1; j > 0; j >>= 1) {
                int t = tid;
                int i = (t << 1) - (t & (j - 1));
                bool desc = (((cbase + i) & k) == 0);
                unsigned long long x = sk[i], y = sk[i + j];
                if ((x < y) == desc) { sk[i] = y; sk[i + j] = x; }
                __syncthreads();
            }
        }
        g_sel[cbase + tid]        = sk[tid];
        g_sel[cbase + tid + 1024] = sk[tid + 1024];
        sync4(10);

        {
            int t4 = (b << 10) + tid;
            int i = (t4 << 1) - (t4 & 2047);
            bool desc = ((i & 4096) == 0);
            unsigned long long x = g_sel[i], y = g_sel[i + 2048];
            if ((x < y) == desc) { g_sel[i] = y; g_sel[i + 2048] = x; }
        }
        sync4(11);

        sk[tid]        = g_sel[cbase + tid];
        sk[tid + 1024] = g_sel[cbase + tid + 1024];
        __syncthreads();
        for (int j = 1024; j > 0; j >>= 1) {
            int t = tid;
            int i = (t << 1) - (t & (j - 1));
            bool desc = (((cbase + i) & 4096) == 0);
            unsigned long long x = sk[i], y = sk[i + j];
            if ((x < y) == desc) { sk[i] = y; sk[i + j] = x; }
            __syncthreads();
        }
        g_sel[cbase + tid]        = sk[tid];
        g_sel[cbase + tid + 1024] = sk[tid + 1024];
        sync4(12);

        {
            int t4 = (b << 10) + tid;
            unsigned long long x = g_sel[t4], y = g_sel[t4 + 4096];
            if (x < y) { g_sel[t4] = y; g_sel[t4 + 4096] = x; }
        }
        sync4(13);

        {
            int t4 = (b << 10) + tid;
            int i = (t4 << 1) - (t4 & 2047);
            unsigned long long x = g_sel[i], y = g_sel[i + 2048];
            if (x < y) { g_sel[i] = y; g_sel[i + 2048] = x; }
        }
        sync4(14);

        sk[tid]        = g_sel[cbase + tid];
        sk[tid + 1024] = g_sel[cbase + tid + 1024];
        __syncthreads();
        for (int j = 1024; j > 0; j >>= 1) {
            int t = tid;
            int i = (t << 1) - (t & (j - 1));
            unsigned long long x = sk[i], y = sk[i + j];
            if (x < y) { sk[i] = y; sk[i + j] = x; }
            __syncthreads();
        }
        g_sel[cbase + tid]        = sk[tid];
        g_sel[cbase + tid + 1024] = sk[tid + 1024];
    }
    gsync(5);

    // ---- G+H merged: every block gathers sorted boxes into its smem ----
    float4* sb4 = (float4*)dsm;
    float* sar2 = (float*)(dsm + 96000);
    for (int j = tid; j < TOPK; j += 1024) {
        unsigned long long key = g_sel[j];
        unsigned idx = 0xFFFFFFFFu - (unsigned)(key & 0xFFFFFFFFull);
        float4 bx = make_float4(0.f, 0.f, 0.f, 0.f);
        float ar = -1.f;
        if (idx < (unsigned)NANCH) {
            bx = make_float4(g_dx1[idx], g_dy1[idx], g_dx2[idx], g_dy2[idx]);
            ar = g_dar[idx];
        }
        sb4[j] = bx;
        sar2[j] = ar;
    }
    __syncthreads();

    mat_rows(sb4, sar2, 0, CHUNK, b * 1024 + tid, GRIDT * 1024);
    gsync(6);

    // ---- worker pool (blocks 1..147) ----
    if (b != 0) {
        __shared__ int cmd;
        int next = 1;
        for (;;) {
            if (tid == 0) {
                int w;
                for (;;) {
                    w = *(volatile int*)&g_work;
                    if (w == -1 || w >= next) break;
                    __nanosleep(128);
                }
                cmd = w;
            }
            __syncthreads();
            int w = cmd;
            if (w == -1) return;
            int r0 = next * CHUNK;
            int r1 = min(r0 + CHUNK, TOPK);
            mat_rows(sb4, sar2, r0, r1, (b - 1) * 1024 + tid, (GRIDT - 1) * 1024);
            __threadfence();
            __syncthreads();
            if (tid == 0) atomicAdd(&g_bars[20 + next], 1);
            next++;
            if (next >= NCHUNK) return;
        }
    }

    // ---- I (block 0): warp-level greedy with register bitmap + prefetch ----
    unsigned* removed = (unsigned*)(dsm + 120064);
    __shared__ int keepList[POSTK];
    __shared__ int cnt_sm;
    {
        const int warpid = tid >> 5, lane = tid & 31;
#pragma unroll
        for (int q = 0; q < 6; q++) {
            int wd = q * 32 + warpid;
            if (wd < NBITW) {
                int j = (wd << 5) + lane;
                bool bad = (j >= TOPK) || (sar2[j] < 0.f);
                unsigned m = __ballot_sync(0xFFFFFFFFu, bad);
                if (lane == 0) removed[wd] = m;
            }
        }
    }
    __syncthreads();

    if (tid < 32) {
        unsigned rem[6];
#pragma unroll
        for (int q = 0; q < 6; q++) {
            int wd = tid * 6 + q;
            rem[q] = (wd < NBITW) ? removed[wd] : 0xFFFFFFFFu;
        }
        int count = 0, limit = CHUNK;
        int preidx = -1;
        unsigned pre[6] = {0, 0, 0, 0, 0, 0};
        for (;;) {
            int pos = 0x7FFFFFFF;
#pragma unroll
            for (int q = 0; q < 6; q++) {
                unsigned w = ~rem[q];
                if (w != 0u && pos == 0x7FFFFFFF)
                    pos = (tid * 6 + q) * 32 + (__ffs(w) - 1);
            }
            int i = __reduce_min_sync(0xFFFFFFFFu, pos);
            if (i >= TOPK) break;
            while (i >= limit) {
                int k = limit / CHUNK;
                if (tid == 0) {
                    atomicExch(&g_work, k);
                    while (*(volatile int*)&g_bars[20 + k] < GRIDT - 1) { __nanosleep(128); }
                }
                __syncwarp();
                __threadfence();
                limit += CHUNK;
            }
            if (tid == 0) keepList[count] = i;
            count++;
            if (count >= POSTK) break;
            {
                int ow = i >> 5;
                if (tid == ow / 6) rem[ow % 6] |= 1u << (i & 31);
            }
            unsigned cur[6];
            if (i == preidx) {
#pragma unroll
                for (int q = 0; q < 6; q++) cur[q] = pre[q];
            } else {
                const unsigned* rowp = &g_mat[(size_t)i * NBITW];
#pragma unroll
                for (int q = 0; q < 6; q++) {
                    int wd = tid * 6 + q;
                    cur[q] = (wd < NBITW) ? rowp[wd] : 0u;
                }
            }
            int ni = i + 1;
            if (ni < TOPK && ni < limit) {
                const unsigned* rowp = &g_mat[(size_t)ni * NBITW];
#pragma unroll
                for (int q = 0; q < 6; q++) {
                    int wd = tid * 6 + q;
                    pre[q] = (wd < NBITW) ? rowp[wd] : 0u;
                }
                preidx = ni;
            } else {
                preidx = -1;
            }
#pragma unroll
            for (int q = 0; q < 6; q++) rem[q] |= cur[q];
        }
        if (tid == 0) { cnt_sm = count; atomicExch(&g_work, -1); }
    }
    __syncthreads();

    const int count = cnt_sm;
    for (int t = tid; t < POSTK; t += 1024) {
        if (t < count) {
            int ii = keepList[t];
            float4 bb4 = sb4[ii];
            unsigned long long key = g_sel[ii];
            unsigned u = (unsigned)(key >> 32);
            unsigned bb = (u & 0x80000000u) ? (u & 0x7FFFFFFFu) : ~u;
            float cls = __uint_as_float(bb);
            float sc = (float)(1.0 / (1.0 + exp(-(double)cls)));
            out[t * 5 + 0] = bb4.x;
            out[t * 5 + 1] = bb4.y;
            out[t * 5 + 2] = bb4.z;
            out[t * 5 + 3] = bb4.w;
            out[t * 5 + 4] = sc;
        } else {
            out[t * 5 + 0] = 0.f; out[t * 5 + 1] = 0.f; out[t * 5 + 2] = 0.f;
            out[t * 5 + 3] = 0.f; out[t * 5 + 4] = 0.f;
        }
    }
}

// ---------------- launch ----------------
extern "C" void kernel_launch(void* const* d_in, const int* in_sizes, int n_in,
                              void* d_out, int out_size)
{
    (void)in_sizes; (void)n_in; (void)out_size;
    const float* feat   = (const float*)d_in[1];
    const float* conv_w = (const float*)d_in[2];
    const float* conv_b = (const float*)d_in[3];
    const float* cls_w  = (const float*)d_in[4];
    const float* cls_b  = (const float*)d_in[5];
    const float* bbox_w = (const float*)d_in[6];
    const float* bbox_b = (const float*)d_in[7];
    float* out = (float*)d_out;

    prep_all<<<4371, 1024>>>(feat, conv_w);

    cudaFuncSetAttribute(conv_mma, cudaFuncAttributeMaxDynamicSharedMemorySize, DYNSM);
    conv_mma<<<dim3(64, 2), 512, DYNSM>>>(conv_b);

    cudaFuncSetAttribute(heads_sums, cudaFuncAttributeMaxDynamicSharedMemorySize, HSM_BYTES);
    heads_sums<<<1024, 256, HSM_BYTES>>>(cls_w, cls_b, bbox_w, bbox_b);

    cudaFuncSetAttribute(tail, cudaFuncAttributeMaxDynamicSharedMemorySize, TAILSM);
    tail<<<GRIDT, 1024, TAILSM>>>(out);
}